// round 12
// baseline (speedup 1.0000x reference)
#include <cuda_runtime.h>
#include <cuda_fp16.h>
#include <math.h>
#include <stdint.h>

#define BATCH 2048
#define CTRLN 512
#define MEMN  1024
#define VDIM  64
#define KCAT  640
#define SPLITK 8

// ---------------- scratch (device globals: allocation-free) ----------------
__device__ __half g_acat[BATCH * KCAT];
__device__ __half g_wcat[2048 * KCAT];       // gate-interleaved [W_ih|W_hh]
__device__ __half g_wrw[2048 * CTRLN];
__device__ __half g_wea[128 * CTRLN];
__device__ __half g_wout[64 * (CTRLN + 64)];
__device__ __half g_memT[64 * MEMN];
__device__ __half g_rwph[BATCH * MEMN];
__device__ __half g_logits[BATCH * 2048];
__device__ __half g_ht16[BATCH * CTRLN];
__device__ __half g_readw[BATCH * MEMN];
__device__ __half g_rw[BATCH * MEMN];
__device__ float  g_s[BATCH];
__device__ __half g_readnew[BATCH * VDIM];
__device__ float  g_p1[SPLITK * BATCH * VDIM];
__device__ float  g_p2[SPLITK * BATCH * VDIM];
__device__ float  g_p3[SPLITK * BATCH * 128];
__device__ float  g_p4[SPLITK * BATCH * VDIM];   // out-GEMM ht-phase partials

// ---------------- helpers ----------------------------------------------------
__device__ __forceinline__ uint32_t smem_u32(const void* p) {
    uint32_t a;
    asm("{ .reg .u64 t; cvta.to.shared.u64 t, %1; cvt.u32.u64 %0, t; }"
        : "=r"(a) : "l"(p));
    return a;
}
__device__ __forceinline__ uint2 h4(float4 v) {
    __half2 a = __floats2half2_rn(v.x, v.y);
    __half2 b = __floats2half2_rn(v.z, v.w);
    uint2 r;
    r.x = *(uint32_t*)&a;
    r.y = *(uint32_t*)&b;
    return r;
}
__device__ __forceinline__ float sigf(float x) {
    return __fdividef(1.0f, 1.0f + __expf(-x));
}
__device__ __forceinline__ float tanf_(float x) {
    float e = __expf(-2.0f * fabsf(x));
    float t = __fdividef(1.0f - e, 1.0f + e);
    return copysignf(t, x);
}

#define CP_ASYNC16(s, g) \
    asm volatile("cp.async.cg.shared.global [%0], [%1], 16;" \
                 :: "r"(s), "l"(g) : "memory")
#define CP_COMMIT() asm volatile("cp.async.commit_group;" ::: "memory")
#define CP_WAIT1()  asm volatile("cp.async.wait_group 1;" ::: "memory")
#define CP_WAIT0()  asm volatile("cp.async.wait_group 0;" ::: "memory")

#define LDMX4(r0, r1, r2, r3, a) \
    asm volatile("ldmatrix.sync.aligned.m8n8.x4.shared.b16 {%0,%1,%2,%3}, [%4];" \
                 : "=r"(r0), "=r"(r1), "=r"(r2), "=r"(r3) : "r"(a))

#define MMA16(d, a, b0, b1) \
    asm volatile("mma.sync.aligned.m16n8k16.row.col.f32.f16.f16.f32 " \
        "{%0,%1,%2,%3}, {%4,%5,%6,%7}, {%8,%9}, {%0,%1,%2,%3};" \
        : "+f"((d)[0]), "+f"((d)[1]), "+f"((d)[2]), "+f"((d)[3]) \
        : "r"((a)[0]), "r"((a)[1]), "r"((a)[2]), "r"((a)[3]), "r"(b0), "r"(b1))

// ---------------- fp16 big GEMM core: CTA 128x128, BK=64, 3 stages ----------
#define STAGE_SZ 32768
#define SMEM_MMA (3 * STAGE_SZ)

#define MMA_BIG_MAINLOOP(A, W, K)                                              \
    extern __shared__ char smem[];                                             \
    const int tid  = threadIdx.x;                                              \
    const int lane = tid & 31, wid = tid >> 5;                                 \
    const int wm = wid >> 2, wn = wid & 3;                                     \
    const int bm = blockIdx.y, bn = blockIdx.x;                                \
    const uint32_t sbase = smem_u32(smem);                                     \
    const int NT = (K) >> 6;                                                   \
    float acc[4][4][4] = {};                                                   \
    const int lrow = tid >> 1;                                                 \
    const int lc0  = (tid & 1) * 4;                                            \
    const __half* Ag = (A) + (size_t)(bm * 128 + lrow) * (K);                  \
    const __half* Wg = (W) + (size_t)(bn * 128 + lrow) * (K);                  \
    uint32_t sw[4];                                                            \
    _Pragma("unroll")                                                          \
    for (int i = 0; i < 4; i++)                                                \
        sw[i] = (uint32_t)lrow * 128 + (((lc0 + i) ^ (lrow & 7)) * 16);        \
    _Pragma("unroll")                                                          \
    for (int s = 0; s < 2; s++) {                                              \
        uint32_t sA = sbase + s * STAGE_SZ;                                    \
        uint32_t sB = sA + 16384;                                              \
        int k0 = s * 64;                                                       \
        _Pragma("unroll")                                                      \
        for (int i = 0; i < 4; i++) {                                          \
            CP_ASYNC16(sA + sw[i], Ag + k0 + (lc0 + i) * 8);                   \
            CP_ASYNC16(sB + sw[i], Wg + k0 + (lc0 + i) * 8);                   \
        }                                                                      \
        CP_COMMIT();                                                           \
    }                                                                          \
    const int arow = (lane & 15);                                              \
    const int acol = (lane >> 4);                                              \
    const int brow = (lane & 7) + ((lane >> 4) << 3);                          \
    const int bcol = (lane >> 3) & 1;                                          \
    for (int kt = 0; kt < NT; kt++) {                                          \
        CP_WAIT1();                                                            \
        __syncthreads();                                                       \
        if (kt + 2 < NT) {                                                     \
            int st = (kt + 2) % 3;                                             \
            uint32_t sA = sbase + st * STAGE_SZ;                               \
            uint32_t sB = sA + 16384;                                          \
            int k0 = (kt + 2) * 64;                                            \
            _Pragma("unroll")                                                  \
            for (int i = 0; i < 4; i++) {                                      \
                CP_ASYNC16(sA + sw[i], Ag + k0 + (lc0 + i) * 8);               \
                CP_ASYNC16(sB + sw[i], Wg + k0 + (lc0 + i) * 8);               \
            }                                                                  \
            CP_COMMIT();                                                       \
        }                                                                      \
        uint32_t sA = sbase + (kt % 3) * STAGE_SZ;                             \
        uint32_t sB = sA + 16384;                                              \
        _Pragma("unroll")                                                      \
        for (int ks = 0; ks < 4; ks++) {                                       \
            uint32_t af[4][4], bf[2][4];                                       \
            _Pragma("unroll")                                                  \
            for (int mi = 0; mi < 4; mi++) {                                   \
                int r = wm * 64 + mi * 16 + arow;                              \
                int c = 2 * ks + acol;                                         \
                uint32_t addr = sA + r * 128 + ((c ^ (r & 7)) * 16);           \
                LDMX4(af[mi][0], af[mi][1], af[mi][2], af[mi][3], addr);       \
            }                                                                  \
            _Pragma("unroll")                                                  \
            for (int bi = 0; bi < 2; bi++) {                                   \
                int r = wn * 32 + bi * 16 + brow;                              \
                int c = 2 * ks + bcol;                                         \
                uint32_t addr = sB + r * 128 + ((c ^ (r & 7)) * 16);           \
                LDMX4(bf[bi][0], bf[bi][1], bf[bi][2], bf[bi][3], addr);       \
            }                                                                  \
            _Pragma("unroll")                                                  \
            for (int mi = 0; mi < 4; mi++) {                                   \
                _Pragma("unroll")                                              \
                for (int j = 0; j < 4; j++)                                    \
                    MMA16(acc[mi][j], af[mi], bf[j >> 1][(j & 1) * 2],         \
                          bf[j >> 1][(j & 1) * 2 + 1]);                        \
            }                                                                  \
        }                                                                      \
    }

// ---------------- gates GEMM with fused LSTM epilogue ------------------------
__global__ __launch_bounds__(256, 2) void mma_gates(
    const __half* __restrict__ A, const __half* __restrict__ W, int K,
    const float* __restrict__ b_ih, const float* __restrict__ b_hh,
    const float* __restrict__ c_prev, __half* __restrict__ ht)
{
    MMA_BIG_MAINLOOP(A, W, K)

    const int q = lane & 3;
    const int u0 = (bn * 4 + wn) * 8 + q * 2;
    float bsum[4][2];
    #pragma unroll
    for (int j = 0; j < 4; j++)
        #pragma unroll
        for (int uu = 0; uu < 2; uu++) {
            int orig = j * 512 + u0 + uu;
            bsum[j][uu] = b_ih[orig] + b_hh[orig];
        }
    #pragma unroll
    for (int mi = 0; mi < 4; mi++) {
        int r0 = bm * 128 + wm * 64 + mi * 16 + (lane >> 2);
        #pragma unroll
        for (int rr = 0; rr < 2; rr++) {
            int r = r0 + rr * 8;
            float2 cp = *(const float2*)&c_prev[(size_t)r * 512 + u0];
            float cc[2] = {cp.x, cp.y};
            float hv[2];
            #pragma unroll
            for (int uu = 0; uu < 2; uu++) {
                int k = rr * 2 + uu;
                float gi = acc[mi][0][k] + bsum[0][uu];
                float gf = acc[mi][1][k] + bsum[1][uu];
                float gg = acc[mi][2][k] + bsum[2][uu];
                float go = acc[mi][3][k] + bsum[3][uu];
                float c = sigf(gf) * cc[uu] + sigf(gi) * tanf_(gg);
                hv[uu] = sigf(go) * tanf_(c);
            }
            *(__half2*)&ht[(size_t)r * 512 + u0] = __floats2half2_rn(hv[0], hv[1]);
        }
    }
}

// ---------------- logits GEMM (fp16 output, split bias) ----------------------
__global__ __launch_bounds__(256, 2) void mma_logits(
    const __half* __restrict__ A, const __half* __restrict__ W, int K,
    const float* __restrict__ bias_a, const float* __restrict__ bias_b,
    __half* __restrict__ C)
{
    MMA_BIG_MAINLOOP(A, W, K)

    #pragma unroll
    for (int mi = 0; mi < 4; mi++) {
        #pragma unroll
        for (int j = 0; j < 4; j++) {
            int row = bm * 128 + wm * 64 + mi * 16 + (lane >> 2);
            int col = bn * 128 + wn * 32 + j * 8 + (lane & 3) * 2;
            float bv0 = (col < 1024) ? bias_a[col] : bias_b[col - 1024];
            float bv1 = (col + 1 < 1024) ? bias_a[col + 1] : bias_b[col + 1 - 1024];
            *(__half2*)&C[(size_t)row * 2048 + col] =
                __floats2half2_rn(acc[mi][j][0] + bv0, acc[mi][j][1] + bv1);
            *(__half2*)&C[(size_t)(row + 8) * 2048 + col] =
                __floats2half2_rn(acc[mi][j][2] + bv0, acc[mi][j][3] + bv1);
        }
    }
}

// ---------------- fp16 mma skinny split-K (single/concat-A) -----------------
#define SKSTG0 16384

__global__ __launch_bounds__(256) void mma_skinny1(
    const __half* __restrict__ A1, int lda1, int K1,
    const __half* __restrict__ Bw, int ldw, int NB,
    float* __restrict__ P1)
{
    extern __shared__ char smem[];
    const uint32_t sbase = smem_u32(smem);
    const int tid  = threadIdx.x;
    const int lane = tid & 31, wid = tid >> 5;
    const int wm = wid >> 1, wn = wid & 1;
    const int bmRow = (blockIdx.x / NB) * 64;
    const int bn    = (blockIdx.x % NB) * 64;

    const int total_tiles = K1 >> 6;
    const int per = (total_tiles + SPLITK - 1) / SPLITK;
    const int t0 = blockIdx.y * per;
    int t1 = t0 + per; if (t1 > total_tiles) t1 = total_tiles;

    float acc[4][4] = {};
    const int lrow = tid >> 2;
    const int lc0  = (tid & 3) * 2;
    uint32_t sw[2];
    #pragma unroll
    for (int i = 0; i < 2; i++)
        sw[i] = (uint32_t)lrow * 128 + (((lc0 + i) ^ (lrow & 7)) * 16);

    auto load_tile = [&](int t, int stg) {
        const int k0 = t << 6;
        uint32_t sA = sbase + stg * SKSTG0;
        uint32_t sB = sA + 8192;
        const __half* Arow = A1 + (size_t)(bmRow + lrow) * lda1 + k0;
        const __half* Brow = Bw + (size_t)(bn + lrow) * ldw + k0;
        #pragma unroll
        for (int i = 0; i < 2; i++) {
            CP_ASYNC16(sA + sw[i], Arow + (lc0 + i) * 8);
            CP_ASYNC16(sB + sw[i], Brow + (lc0 + i) * 8);
        }
        CP_COMMIT();
    };

    const int arow = (lane & 15);
    const int acol = (lane >> 4);
    const int brow = (lane & 7) + ((lane >> 4) << 3);
    const int bcol = (lane >> 3) & 1;

    if (t0 < t1) {
        load_tile(t0, t0 & 1);
        for (int t = t0; t < t1; t++) {
            if (t + 1 < t1) { load_tile(t + 1, (t + 1) & 1); CP_WAIT1(); }
            else            { CP_WAIT0(); }
            __syncthreads();
            uint32_t sA = sbase + (t & 1) * SKSTG0;
            uint32_t sB = sA + 8192;
            #pragma unroll
            for (int ks = 0; ks < 4; ks++) {
                uint32_t af[4], bf[2][4];
                {
                    int r = wm * 16 + arow;
                    int c = 2 * ks + acol;
                    uint32_t addr = sA + r * 128 + ((c ^ (r & 7)) * 16);
                    LDMX4(af[0], af[1], af[2], af[3], addr);
                }
                #pragma unroll
                for (int bi = 0; bi < 2; bi++) {
                    int r = wn * 32 + bi * 16 + brow;
                    int c = 2 * ks + bcol;
                    uint32_t addr = sB + r * 128 + ((c ^ (r & 7)) * 16);
                    LDMX4(bf[bi][0], bf[bi][1], bf[bi][2], bf[bi][3], addr);
                }
                #pragma unroll
                for (int j = 0; j < 4; j++)
                    MMA16(acc[j], af, bf[j >> 1][(j & 1) * 2],
                          bf[j >> 1][(j & 1) * 2 + 1]);
            }
            __syncthreads();
        }
    }

    const int pw = NB * 64;
    #pragma unroll
    for (int j = 0; j < 4; j++) {
        int row = bmRow + wm * 16 + (lane >> 2);
        int col = bn + wn * 32 + j * 8 + (lane & 3) * 2;
        size_t base = ((size_t)blockIdx.y * BATCH + row) * pw + col;
        *(float2*)&P1[base]          = make_float2(acc[j][0], acc[j][1]);
        *(float2*)&P1[base + 8 * pw] = make_float2(acc[j][2], acc[j][3]);
    }
}

// ---------------- dual skinny: (readw,rw)@memT^T ------------------------------
#define SKSTG1 24576

__global__ __launch_bounds__(256) void mma_skinny_dual(
    const __half* __restrict__ readw, const __half* __restrict__ rw,
    const __half* __restrict__ memT,
    float* __restrict__ P1, float* __restrict__ P2)
{
    extern __shared__ char smem[];
    const uint32_t sbase = smem_u32(smem);
    const int tid  = threadIdx.x;
    const int lane = tid & 31, wid = tid >> 5;
    const int wm = wid >> 1, wn = wid & 1;
    const int bmRow = blockIdx.x * 64;
    const int bn    = 0;

    const int total_tiles = MEMN >> 6;
    const int per = (total_tiles + SPLITK - 1) / SPLITK;
    const int t0 = blockIdx.y * per;
    int t1 = t0 + per; if (t1 > total_tiles) t1 = total_tiles;

    float acc[4][4] = {};
    float accd[4][4] = {};
    const int lrow = tid >> 2;
    const int lc0  = (tid & 3) * 2;
    uint32_t sw[2];
    #pragma unroll
    for (int i = 0; i < 2; i++)
        sw[i] = (uint32_t)lrow * 128 + (((lc0 + i) ^ (lrow & 7)) * 16);

    auto load_tile = [&](int t, int stg) {
        int k0 = t << 6;
        uint32_t sA  = sbase + stg * SKSTG1;
        uint32_t sAd = sA + 8192;
        uint32_t sB  = sA + 16384;
        const __half* Arow  = readw + (size_t)(bmRow + lrow) * MEMN + k0;
        const __half* Adrow = rw    + (size_t)(bmRow + lrow) * MEMN + k0;
        const __half* Brow  = memT  + (size_t)(bn + lrow) * MEMN + k0;
        #pragma unroll
        for (int i = 0; i < 2; i++) {
            CP_ASYNC16(sA + sw[i],  Arow  + (lc0 + i) * 8);
            CP_ASYNC16(sAd + sw[i], Adrow + (lc0 + i) * 8);
            CP_ASYNC16(sB + sw[i],  Brow  + (lc0 + i) * 8);
        }
        CP_COMMIT();
    };

    const int arow = (lane & 15);
    const int acol = (lane >> 4);
    const int brow = (lane & 7) + ((lane >> 4) << 3);
    const int bcol = (lane >> 3) & 1;

    if (t0 < t1) {
        load_tile(t0, t0 & 1);
        for (int t = t0; t < t1; t++) {
            if (t + 1 < t1) { load_tile(t + 1, (t + 1) & 1); CP_WAIT1(); }
            else            { CP_WAIT0(); }
            __syncthreads();
            uint32_t sA  = sbase + (t & 1) * SKSTG1;
            uint32_t sAd = sA + 8192;
            uint32_t sB  = sA + 16384;
            #pragma unroll
            for (int ks = 0; ks < 4; ks++) {
                uint32_t af[4], afd[4], bf[2][4];
                {
                    int r = wm * 16 + arow;
                    int c = 2 * ks + acol;
                    uint32_t addr = sA + r * 128 + ((c ^ (r & 7)) * 16);
                    LDMX4(af[0], af[1], af[2], af[3], addr);
                    uint32_t addrd = sAd + r * 128 + ((c ^ (r & 7)) * 16);
                    LDMX4(afd[0], afd[1], afd[2], afd[3], addrd);
                }
                #pragma unroll
                for (int bi = 0; bi < 2; bi++) {
                    int r = wn * 32 + bi * 16 + brow;
                    int c = 2 * ks + bcol;
                    uint32_t addr = sB + r * 128 + ((c ^ (r & 7)) * 16);
                    LDMX4(bf[bi][0], bf[bi][1], bf[bi][2], bf[bi][3], addr);
                }
                #pragma unroll
                for (int j = 0; j < 4; j++) {
                    MMA16(acc[j], af, bf[j >> 1][(j & 1) * 2],
                          bf[j >> 1][(j & 1) * 2 + 1]);
                    MMA16(accd[j], afd, bf[j >> 1][(j & 1) * 2],
                          bf[j >> 1][(j & 1) * 2 + 1]);
                }
            }
            __syncthreads();
        }
    }

    #pragma unroll
    for (int j = 0; j < 4; j++) {
        int row = bmRow + wm * 16 + (lane >> 2);
        int col = wn * 32 + j * 8 + (lane & 3) * 2;
        size_t base = ((size_t)blockIdx.y * BATCH + row) * 64 + col;
        *(float2*)&P1[base]          = make_float2(acc[j][0], acc[j][1]);
        *(float2*)&P1[base + 8 * 64] = make_float2(acc[j][2], acc[j][3]);
        *(float2*)&P2[base]          = make_float2(accd[j][0], accd[j][1]);
        *(float2*)&P2[base + 8 * 64] = make_float2(accd[j][2], accd[j][3]);
    }
}

// ---------------- reduces ----------------------------------------------------
__global__ void reduce_act(const float* __restrict__ P,
                           __half* __restrict__ outh, int ldc, int coloff)
{
    int idx = blockIdx.x * blockDim.x + threadIdx.x;   // BATCH*16
    int r = idx >> 4, c = (idx & 15) * 4;
    float4 s = {0.f, 0.f, 0.f, 0.f};
    #pragma unroll
    for (int k = 0; k < SPLITK; k++) {
        float4 v = *(const float4*)&P[((size_t)k * BATCH + r) * 64 + c];
        s.x += v.x; s.y += v.y; s.z += v.z; s.w += v.w;
    }
    *(uint2*)&outh[(size_t)r * ldc + coloff + c] = h4(s);
}

__global__ void reduce_readnew(const float* __restrict__ PA,
                               const float* __restrict__ PB,
                               const float* __restrict__ PE,
                               const float* __restrict__ b_erase,
                               const float* __restrict__ b_add,
                               const float* __restrict__ svec,
                               __half* __restrict__ rn)
{
    int idx = blockIdx.x * blockDim.x + threadIdx.x;   // BATCH*16
    int r = idx >> 4, c = (idx & 15) * 4;
    float4 s1 = {0.f, 0.f, 0.f, 0.f}, s2 = {0.f, 0.f, 0.f, 0.f};
    float4 se = {0.f, 0.f, 0.f, 0.f}, sa = {0.f, 0.f, 0.f, 0.f};
    #pragma unroll
    for (int k = 0; k < SPLITK; k++) {
        float4 v = *(const float4*)&PA[((size_t)k * BATCH + r) * 64 + c];
        float4 u = *(const float4*)&PB[((size_t)k * BATCH + r) * 64 + c];
        float4 e = *(const float4*)&PE[((size_t)k * BATCH + r) * 128 + c];
        float4 a = *(const float4*)&PE[((size_t)k * BATCH + r) * 128 + 64 + c];
        s1.x += v.x; s1.y += v.y; s1.z += v.z; s1.w += v.w;
        s2.x += u.x; s2.y += u.y; s2.z += u.z; s2.w += u.w;
        se.x += e.x; se.y += e.y; se.z += e.z; se.w += e.w;
        sa.x += a.x; sa.y += a.y; sa.z += a.z; sa.w += a.w;
    }
    float sv = svec[r];
    float ev[4] = {se.x, se.y, se.z, se.w};
    float av[4] = {sa.x, sa.y, sa.z, sa.w};
    float v1[4] = {s1.x, s1.y, s1.z, s1.w};
    float v2[4] = {s2.x, s2.y, s2.z, s2.w};
    float4 o;
    float* op = &o.x;
    #pragma unroll
    for (int q = 0; q < 4; q++) {
        float e = sigf(ev[q] + b_erase[c + q]);
        float a = tanf_(av[q] + b_add[c + q]);
        op[q] = v1[q] - e * v2[q] + a * sv;
    }
    *(uint2*)&rn[(size_t)r * 64 + c] = h4(o);
}

// out[r][c] = sum_k P4[k][r][c] + sum_v rn[r][v]*wout[c][512+v] + b_out[c]
__global__ void reduce_out(const float* __restrict__ P4,
                           const __half* __restrict__ rn,
                           const __half* __restrict__ wout,
                           const float* __restrict__ b_out,
                           float* __restrict__ out)
{
    int idx = blockIdx.x * blockDim.x + threadIdx.x;   // BATCH*16
    int r = idx >> 4, c = (idx & 15) * 4;
    float4 s = {0.f, 0.f, 0.f, 0.f};
    #pragma unroll
    for (int k = 0; k < SPLITK; k++) {
        float4 v = *(const float4*)&P4[((size_t)k * BATCH + r) * 64 + c];
        s.x += v.x; s.y += v.y; s.z += v.z; s.w += v.w;
    }
    float a0 = s.x + b_out[c],     a1 = s.y + b_out[c + 1];
    float a2 = s.z + b_out[c + 2], a3 = s.w + b_out[c + 3];
    const __half* rrow = rn + (size_t)r * 64;
    const __half* w0 = wout + (size_t)(c + 0) * 576 + 512;
    const __half* w1 = wout + (size_t)(c + 1) * 576 + 512;
    const __half* w2 = wout + (size_t)(c + 2) * 576 + 512;
    const __half* w3 = wout + (size_t)(c + 3) * 576 + 512;
    #pragma unroll
    for (int v = 0; v < 64; v++) {
        float rv = __half2float(rrow[v]);
        a0 += rv * __half2float(w0[v]);
        a1 += rv * __half2float(w1[v]);
        a2 += rv * __half2float(w2[v]);
        a3 += rv * __half2float(w3[v]);
    }
    *(float4*)&out[(size_t)r * 64 + c] = make_float4(a0, a1, a2, a3);
}

// ---------------- pack kernels ------------------------------------------------
// pack_crit: acat (x|h_prev) + rwp + memT (critical path inputs)
#define N_ACAT_F4  (BATCH * 144)
#define N_RWP_F4   (BATCH * 256)
#define N_CRIT_BLK ((N_ACAT_F4 + N_RWP_F4) / 256)   // 3200
#define N_MEMT_BLK 64

__global__ void pack_crit(const float* __restrict__ x,
                          const float* __restrict__ h_prev,
                          const float* __restrict__ rwp,
                          const float* __restrict__ mem,
                          __half* __restrict__ acat, __half* __restrict__ rwph,
                          __half* __restrict__ memT)
{
    __shared__ float s[32][33];
    if (blockIdx.x >= N_CRIT_BLK) {
        int bxm = blockIdx.x - N_CRIT_BLK;
        int k0 = (bxm & 31) * 32, v0 = (bxm >> 5) * 32;
        int tx = threadIdx.x & 31, ty = threadIdx.x >> 5;
        #pragma unroll
        for (int i = 0; i < 4; i++)
            s[ty + i * 8][tx] = mem[(size_t)(k0 + ty + i * 8) * 64 + v0 + tx];
        __syncthreads();
        #pragma unroll
        for (int i = 0; i < 4; i++)
            memT[(size_t)(v0 + ty + i * 8) * MEMN + k0 + tx] =
                __float2half_rn(s[tx][ty + i * 8]);
        return;
    }
    int idx = blockIdx.x * 256 + threadIdx.x;
    if (idx < N_ACAT_F4) {
        int b = idx / 144, q = idx % 144;
        float4 v; int col;
        if (q < 16) { v = *(const float4*)&x[(size_t)b * 64 + q * 4]; col = q * 4; }
        else { v = *(const float4*)&h_prev[(size_t)b * 512 + (q - 16) * 4];
               col = 128 + (q - 16) * 4; }
        *(uint2*)&acat[(size_t)b * KCAT + col] = h4(v);
        return;
    }
    idx -= N_ACAT_F4;
    {
        float4 v = *(const float4*)&rwp[(size_t)idx * 4];
        *(uint2*)&rwph[(size_t)idx * 4] = h4(v);
    }
}

// pack_rest: weights (wcat gate-interleaved, wrw, wea, wout)
#define N_WCAT_F4  (2048 * 160)
#define N_WRW_F4   (2048 * 128)
#define N_WEAO_F4  25600
#define N_REST_BLK ((N_WCAT_F4 + N_WRW_F4 + N_WEAO_F4) / 256)   // 2404

__global__ void pack_rest(const float* __restrict__ W_ih,
                          const float* __restrict__ W_hh,
                          const float* __restrict__ W_read,
                          const float* __restrict__ W_write,
                          const float* __restrict__ W_erase,
                          const float* __restrict__ W_add,
                          const float* __restrict__ W_out,
                          __half* __restrict__ wcat, __half* __restrict__ wrw,
                          __half* __restrict__ wea, __half* __restrict__ wout)
{
    int idx = blockIdx.x * 256 + threadIdx.x;
    if (idx < N_WCAT_F4) {
        int n = idx / 160, q = idx % 160;
        int orig = ((n >> 3) & 3) * 512 + ((n >> 5) << 3) + (n & 7);
        float4 v = (q < 32)
            ? *(const float4*)&W_ih[(size_t)orig * 128 + q * 4]
            : *(const float4*)&W_hh[(size_t)orig * 512 + (q - 32) * 4];
        *(uint2*)&wcat[(size_t)n * KCAT + q * 4] = h4(v);
        return;
    }
    idx -= N_WCAT_F4;
    if (idx < N_WRW_F4) {
        int n = idx >> 7, q = idx & 127;
        float4 v = (n < 1024)
            ? *(const float4*)&W_read[(size_t)n * 512 + q * 4]
            : *(const float4*)&W_write[(size_t)(n - 1024) * 512 + q * 4];
        *(uint2*)&wrw[(size_t)n * 512 + q * 4] = h4(v);
        return;
    }
    idx -= N_WRW_F4;
    if (idx < 16384) {
        int n = idx >> 7, q = idx & 127;
        float4 v = (n < 64)
            ? *(const float4*)&W_erase[(size_t)n * 512 + q * 4]
            : *(const float4*)&W_add[(size_t)(n - 64) * 512 + q * 4];
        *(uint2*)&wea[(size_t)n * 512 + q * 4] = h4(v);
    } else {
        int j = idx - 16384;
        float4 v = *(const float4*)&W_out[(size_t)j * 4];
        *(uint2*)&wout[(size_t)j * 4] = h4(v);
    }
}

// ---------------- softmax -----------------------------------------------------
__device__ __forceinline__ float blk_reduce(float v, bool mx, float* sh)
{
    int lane = threadIdx.x & 31, wid = threadIdx.x >> 5;
    #pragma unroll
    for (int o = 16; o > 0; o >>= 1) {
        float t = __shfl_xor_sync(0xFFFFFFFFu, v, o);
        v = mx ? fmaxf(v, t) : (v + t);
    }
    if (lane == 0) sh[wid] = v;
    __syncthreads();
    if (wid == 0) {
        float r = (lane < 8) ? sh[lane] : (mx ? -1e30f : 0.f);
        #pragma unroll
        for (int o = 4; o > 0; o >>= 1) {
            float t = __shfl_xor_sync(0xFFFFFFFFu, r, o);
            r = mx ? fmaxf(r, t) : (r + t);
        }
        if (lane == 0) sh[0] = r;
    }
    __syncthreads();
    float r = sh[0];
    __syncthreads();
    return r;
}

__global__ void softmax_fuse_kernel(const __half* __restrict__ logits,
                                    __half* __restrict__ readw,
                                    __half* __restrict__ rwprod,
                                    float* __restrict__ svec)
{
    __shared__ float sh[8];
    int b = blockIdx.x;
    int t = threadIdx.x;
    const __half* r = logits + (size_t)b * 2048;
    const __half* w = r + 1024;
    float vr[4], vw[4];
    float mr = -1e30f, mw = -1e30f;
    #pragma unroll
    for (int i = 0; i < 4; i++) {
        vr[i] = __half2float(r[t + i * 256]);
        vw[i] = __half2float(w[t + i * 256]);
        mr = fmaxf(mr, vr[i]);  mw = fmaxf(mw, vw[i]);
    }
    mr = blk_reduce(mr, true, sh);
    mw = blk_reduce(mw, true, sh);
    float er[4], ew[4], sr = 0.f, sw = 0.f;
    #pragma unroll
    for (int i = 0; i < 4; i++) {
        er[i] = __expf(vr[i] - mr); sr += er[i];
        ew[i] = __expf(vw[i] - mw); sw += ew[i];
    }
    sr = blk_reduce(sr, false, sh);
    sw = blk_reduce(sw, false, sh);
    float inv_sr = __fdividef(1.0f, sr), inv_sw = __fdividef(1.0f, sw);
    float srw = 0.f;
    #pragma unroll
    for (int i = 0; i < 4; i++) {
        float a = er[i] * inv_sr;
        float p = a * (ew[i] * inv_sw);
        readw[(size_t)b * MEMN + t + i * 256] = __float2half_rn(a);
        rwprod[(size_t)b * MEMN + t + i * 256] = __float2half_rn(p);
        srw += p;
    }
    srw = blk_reduce(srw, false, sh);
    if (t == 0) svec[b] = srw;
}

// ---------------- launch ----------------------------------------------------
extern "C" void kernel_launch(void* const* d_in, const int* in_sizes, int n_in,
                              void* d_out, int out_size)
{
    const float* x       = (const float*)d_in[0];
    const float* h_prev  = (const float*)d_in[1];
    const float* c_prev  = (const float*)d_in[2];
    const float* rwp     = (const float*)d_in[3];
    const float* memory  = (const float*)d_in[4];
    const float* W_ih    = (const float*)d_in[5];
    const float* b_ih    = (const float*)d_in[6];
    const float* W_hh    = (const float*)d_in[7];
    const float* b_hh    = (const float*)d_in[8];
    const float* W_read  = (const float*)d_in[9];
    const float* b_read  = (const float*)d_in[10];
    const float* W_write = (const float*)d_in[11];
    const float* b_write = (const float*)d_in[12];
    const float* W_erase = (const float*)d_in[13];
    const float* b_erase = (const float*)d_in[14];
    const float* W_add   = (const float*)d_in[15];
    const float* b_add   = (const float*)d_in[16];
    const float* W_out   = (const float*)d_in[17];
    const float* b_out   = (const float*)d_in[18];
    float* out = (float*)d_out;

    __half *acat, *wcat, *wrw, *wea, *wout, *memT, *rwph, *ht16, *readw, *rw, *rn, *logits;
    float *svec, *p1, *p2, *p3, *p4;
    cudaGetSymbolAddress((void**)&acat,   g_acat);
    cudaGetSymbolAddress((void**)&wcat,   g_wcat);
    cudaGetSymbolAddress((void**)&wrw,    g_wrw);
    cudaGetSymbolAddress((void**)&wea,    g_wea);
    cudaGetSymbolAddress((void**)&wout,   g_wout);
    cudaGetSymbolAddress((void**)&memT,   g_memT);
    cudaGetSymbolAddress((void**)&rwph,   g_rwph);
    cudaGetSymbolAddress((void**)&logits, g_logits);
    cudaGetSymbolAddress((void**)&ht16,   g_ht16);
    cudaGetSymbolAddress((void**)&readw,  g_readw);
    cudaGetSymbolAddress((void**)&rw,     g_rw);
    cudaGetSymbolAddress((void**)&svec,   g_s);
    cudaGetSymbolAddress((void**)&rn,     g_readnew);
    cudaGetSymbolAddress((void**)&p1,     g_p1);
    cudaGetSymbolAddress((void**)&p2,     g_p2);
    cudaGetSymbolAddress((void**)&p3,     g_p3);
    cudaGetSymbolAddress((void**)&p4,     g_p4);

    cudaFuncSetAttribute(mma_gates, cudaFuncAttributeMaxDynamicSharedMemorySize,
                         SMEM_MMA);
    cudaFuncSetAttribute(mma_logits, cudaFuncAttributeMaxDynamicSharedMemorySize,
                         SMEM_MMA);
    cudaFuncSetAttribute(mma_skinny1,
                         cudaFuncAttributeMaxDynamicSharedMemorySize, 2 * SKSTG0);
    cudaFuncSetAttribute(mma_skinny_dual,
                         cudaFuncAttributeMaxDynamicSharedMemorySize, 2 * SKSTG1);

    const int rgrid = (BATCH * 16) / 256;
    cudaStream_t s2 = cudaStreamPerThread;   // distinct from legacy default

    cudaEvent_t evF, evB, evG, evS;
    cudaEventCreateWithFlags(&evF, cudaEventDisableTiming);
    cudaEventCreateWithFlags(&evB, cudaEventDisableTiming);
    cudaEventCreateWithFlags(&evG, cudaEventDisableTiming);
    cudaEventCreateWithFlags(&evS, cudaEventDisableTiming);

    // fork: weight packs on s2, concurrent with critical-path prologue
    cudaEventRecord(evF, 0);
    cudaStreamWaitEvent(s2, evF, 0);
    pack_rest<<<N_REST_BLK, 256, 0, s2>>>(
        W_ih, W_hh, W_read, W_write, W_erase, W_add, W_out,
        wcat, wrw, wea, wout);
    cudaEventRecord(evB, s2);

    // legacy: critical prologue
    pack_crit<<<N_CRIT_BLK + N_MEMT_BLK, 256>>>(
        x, h_prev, rwp, memory, acat, rwph, memT);
    mma_skinny1<<<dim3(BATCH / 64, SPLITK), 256, 2 * SKSTG0>>>(
        rwph, MEMN, MEMN, memT, MEMN, 1, p1);
    reduce_act<<<rgrid, 256>>>(p1, acat, KCAT, 64);

    // join weights, then gates
    cudaStreamWaitEvent(0, evB, 0);
    mma_gates<<<dim3(16, 16), 256, SMEM_MMA>>>(
        acat, wcat, KCAT, b_ih, b_hh, c_prev, ht16);
    cudaEventRecord(evG, 0);

    // s2: independent post-gates work (wea GEMM + out ht-phase)
    cudaStreamWaitEvent(s2, evG, 0);
    mma_skinny1<<<dim3((BATCH / 64) * 2, SPLITK), 256, 2 * SKSTG0, s2>>>(
        ht16, CTRLN, CTRLN, wea, CTRLN, 2, p3);
    mma_skinny1<<<dim3(BATCH / 64, SPLITK), 256, 2 * SKSTG0, s2>>>(
        ht16, CTRLN, CTRLN, wout, CTRLN + VDIM, 1, p4);
    cudaEventRecord(evS, s2);

    // legacy: logits -> softmax -> dual skinny
    mma_logits<<<dim3(16, 16), 256, SMEM_MMA>>>(
        ht16, wrw, CTRLN, b_read, b_write, logits);
    softmax_fuse_kernel<<<BATCH, 256>>>(logits, readw, rw, svec);
    mma_skinny_dual<<<dim3(BATCH / 64, SPLITK), 256, 2 * SKSTG1>>>(
        readw, rw, memT, p1, p2);

    // join s2, then final reduces
    cudaStreamWaitEvent(0, evS, 0);
    reduce_readnew<<<rgrid, 256>>>(p1, p2, p3, b_erase, b_add, svec, rn);
    reduce_out<<<rgrid, 256>>>(p4, rn, wout, b_out, out);

    cudaEventDestroy(evF);
    cudaEventDestroy(evB);
    cudaEventDestroy(evG);
    cudaEventDestroy(evS);
}

// round 13
// speedup vs baseline: 1.0444x; 1.0444x over previous
#include <cuda_runtime.h>
#include <cuda_fp16.h>
#include <math.h>
#include <stdint.h>

#define BATCH 2048
#define CTRLN 512
#define MEMN  1024
#define VDIM  64
#define KCAT  640
#define SPLITK 8

// ---------------- scratch (device globals: allocation-free) ----------------
__device__ __half g_acat[BATCH * KCAT];
__device__ __half g_wcat[2048 * KCAT];       // gate-interleaved [W_ih|W_hh]
__device__ __half g_wrw[2048 * CTRLN];
__device__ __half g_wea[128 * CTRLN];
__device__ __half g_wout[64 * (CTRLN + 64)];
__device__ __half g_memT[64 * MEMN];
__device__ __half g_rwph[BATCH * MEMN];
__device__ __half g_logits[BATCH * 2048];
__device__ __half g_ht16[BATCH * CTRLN];
__device__ __half g_readw[BATCH * MEMN];
__device__ __half g_rw[BATCH * MEMN];
__device__ float  g_s[BATCH];
__device__ float  g_p1[SPLITK * BATCH * VDIM];
__device__ float  g_p2[SPLITK * BATCH * VDIM];
__device__ float  g_p3[SPLITK * BATCH * 128];
__device__ float  g_p4[SPLITK * BATCH * VDIM];

// ---------------- helpers ----------------------------------------------------
__device__ __forceinline__ uint32_t smem_u32(const void* p) {
    uint32_t a;
    asm("{ .reg .u64 t; cvta.to.shared.u64 t, %1; cvt.u32.u64 %0, t; }"
        : "=r"(a) : "l"(p));
    return a;
}
__device__ __forceinline__ uint2 h4(float4 v) {
    __half2 a = __floats2half2_rn(v.x, v.y);
    __half2 b = __floats2half2_rn(v.z, v.w);
    uint2 r;
    r.x = *(uint32_t*)&a;
    r.y = *(uint32_t*)&b;
    return r;
}
__device__ __forceinline__ float sigf(float x) {
    return __fdividef(1.0f, 1.0f + __expf(-x));
}
__device__ __forceinline__ float tanf_(float x) {
    float e = __expf(-2.0f * fabsf(x));
    float t = __fdividef(1.0f - e, 1.0f + e);
    return copysignf(t, x);
}

#define CP_ASYNC16(s, g) \
    asm volatile("cp.async.cg.shared.global [%0], [%1], 16;" \
                 :: "r"(s), "l"(g) : "memory")
#define CP_COMMIT() asm volatile("cp.async.commit_group;" ::: "memory")
#define CP_WAIT1()  asm volatile("cp.async.wait_group 1;" ::: "memory")
#define CP_WAIT0()  asm volatile("cp.async.wait_group 0;" ::: "memory")

#define LDMX4(r0, r1, r2, r3, a) \
    asm volatile("ldmatrix.sync.aligned.m8n8.x4.shared.b16 {%0,%1,%2,%3}, [%4];" \
                 : "=r"(r0), "=r"(r1), "=r"(r2), "=r"(r3) : "r"(a))

#define MMA16(d, a, b0, b1) \
    asm volatile("mma.sync.aligned.m16n8k16.row.col.f32.f16.f16.f32 " \
        "{%0,%1,%2,%3}, {%4,%5,%6,%7}, {%8,%9}, {%0,%1,%2,%3};" \
        : "+f"((d)[0]), "+f"((d)[1]), "+f"((d)[2]), "+f"((d)[3]) \
        : "r"((a)[0]), "r"((a)[1]), "r"((a)[2]), "r"((a)[3]), "r"(b0), "r"(b1))

// ---------------- fp16 big GEMM core: CTA 128x128, BK=64, 3 stages ----------
#define STAGE_SZ 32768
#define SMEM_MMA (3 * STAGE_SZ)

#define MMA_BIG_MAINLOOP(A, W, K)                                              \
    extern __shared__ char smem[];                                             \
    const int tid  = threadIdx.x;                                              \
    const int lane = tid & 31, wid = tid >> 5;                                 \
    const int wm = wid >> 2, wn = wid & 3;                                     \
    const int bm = blockIdx.y, bn = blockIdx.x;                                \
    const uint32_t sbase = smem_u32(smem);                                     \
    const int NT = (K) >> 6;                                                   \
    float acc[4][4][4] = {};                                                   \
    const int lrow = tid >> 1;                                                 \
    const int lc0  = (tid & 1) * 4;                                            \
    const __half* Ag = (A) + (size_t)(bm * 128 + lrow) * (K);                  \
    const __half* Wg = (W) + (size_t)(bn * 128 + lrow) * (K);                  \
    uint32_t sw[4];                                                            \
    _Pragma("unroll")                                                          \
    for (int i = 0; i < 4; i++)                                                \
        sw[i] = (uint32_t)lrow * 128 + (((lc0 + i) ^ (lrow & 7)) * 16);        \
    _Pragma("unroll")                                                          \
    for (int s = 0; s < 2; s++) {                                              \
        uint32_t sA = sbase + s * STAGE_SZ;                                    \
        uint32_t sB = sA + 16384;                                              \
        int k0 = s * 64;                                                       \
        _Pragma("unroll")                                                      \
        for (int i = 0; i < 4; i++) {                                          \
            CP_ASYNC16(sA + sw[i], Ag + k0 + (lc0 + i) * 8);                   \
            CP_ASYNC16(sB + sw[i], Wg + k0 + (lc0 + i) * 8);                   \
        }                                                                      \
        CP_COMMIT();                                                           \
    }                                                                          \
    const int arow = (lane & 15);                                              \
    const int acol = (lane >> 4);                                              \
    const int brow = (lane & 7) + ((lane >> 4) << 3);                          \
    const int bcol = (lane >> 3) & 1;                                          \
    for (int kt = 0; kt < NT; kt++) {                                          \
        CP_WAIT1();                                                            \
        __syncthreads();                                                       \
        if (kt + 2 < NT) {                                                     \
            int st = (kt + 2) % 3;                                             \
            uint32_t sA = sbase + st * STAGE_SZ;                               \
            uint32_t sB = sA + 16384;                                          \
            int k0 = (kt + 2) * 64;                                            \
            _Pragma("unroll")                                                  \
            for (int i = 0; i < 4; i++) {                                      \
                CP_ASYNC16(sA + sw[i], Ag + k0 + (lc0 + i) * 8);               \
                CP_ASYNC16(sB + sw[i], Wg + k0 + (lc0 + i) * 8);               \
            }                                                                  \
            CP_COMMIT();                                                       \
        }                                                                      \
        uint32_t sA = sbase + (kt % 3) * STAGE_SZ;                             \
        uint32_t sB = sA + 16384;                                              \
        _Pragma("unroll")                                                      \
        for (int ks = 0; ks < 4; ks++) {                                       \
            uint32_t af[4][4], bf[2][4];                                       \
            _Pragma("unroll")                                                  \
            for (int mi = 0; mi < 4; mi++) {                                   \
                int r = wm * 64 + mi * 16 + arow;                              \
                int c = 2 * ks + acol;                                         \
                uint32_t addr = sA + r * 128 + ((c ^ (r & 7)) * 16);           \
                LDMX4(af[mi][0], af[mi][1], af[mi][2], af[mi][3], addr);       \
            }                                                                  \
            _Pragma("unroll")                                                  \
            for (int bi = 0; bi < 2; bi++) {                                   \
                int r = wn * 32 + bi * 16 + brow;                              \
                int c = 2 * ks + bcol;                                         \
                uint32_t addr = sB + r * 128 + ((c ^ (r & 7)) * 16);           \
                LDMX4(bf[bi][0], bf[bi][1], bf[bi][2], bf[bi][3], addr);       \
            }                                                                  \
            _Pragma("unroll")                                                  \
            for (int mi = 0; mi < 4; mi++) {                                   \
                _Pragma("unroll")                                              \
                for (int j = 0; j < 4; j++)                                    \
                    MMA16(acc[mi][j], af[mi], bf[j >> 1][(j & 1) * 2],         \
                          bf[j >> 1][(j & 1) * 2 + 1]);                        \
            }                                                                  \
        }                                                                      \
    }

// ---------------- gates GEMM with fused LSTM epilogue ------------------------
__global__ __launch_bounds__(256, 2) void mma_gates(
    const __half* __restrict__ A, const __half* __restrict__ W, int K,
    const float* __restrict__ b_ih, const float* __restrict__ b_hh,
    const float* __restrict__ c_prev, __half* __restrict__ ht)
{
    MMA_BIG_MAINLOOP(A, W, K)

    const int q = lane & 3;
    const int u0 = (bn * 4 + wn) * 8 + q * 2;
    float bsum[4][2];
    #pragma unroll
    for (int j = 0; j < 4; j++)
        #pragma unroll
        for (int uu = 0; uu < 2; uu++) {
            int orig = j * 512 + u0 + uu;
            bsum[j][uu] = b_ih[orig] + b_hh[orig];
        }
    #pragma unroll
    for (int mi = 0; mi < 4; mi++) {
        int r0 = bm * 128 + wm * 64 + mi * 16 + (lane >> 2);
        #pragma unroll
        for (int rr = 0; rr < 2; rr++) {
            int r = r0 + rr * 8;
            float2 cp = *(const float2*)&c_prev[(size_t)r * 512 + u0];
            float cc[2] = {cp.x, cp.y};
            float hv[2];
            #pragma unroll
            for (int uu = 0; uu < 2; uu++) {
                int k = rr * 2 + uu;
                float gi = acc[mi][0][k] + bsum[0][uu];
                float gf = acc[mi][1][k] + bsum[1][uu];
                float gg = acc[mi][2][k] + bsum[2][uu];
                float go = acc[mi][3][k] + bsum[3][uu];
                float c = sigf(gf) * cc[uu] + sigf(gi) * tanf_(gg);
                hv[uu] = sigf(go) * tanf_(c);
            }
            *(__half2*)&ht[(size_t)r * 512 + u0] = __floats2half2_rn(hv[0], hv[1]);
        }
    }
}

// ---------------- logits GEMM (fp16 output, split bias) ----------------------
__global__ __launch_bounds__(256, 2) void mma_logits(
    const __half* __restrict__ A, const __half* __restrict__ W, int K,
    const float* __restrict__ bias_a, const float* __restrict__ bias_b,
    __half* __restrict__ C)
{
    MMA_BIG_MAINLOOP(A, W, K)

    #pragma unroll
    for (int mi = 0; mi < 4; mi++) {
        #pragma unroll
        for (int j = 0; j < 4; j++) {
            int row = bm * 128 + wm * 64 + mi * 16 + (lane >> 2);
            int col = bn * 128 + wn * 32 + j * 8 + (lane & 3) * 2;
            float bv0 = (col < 1024) ? bias_a[col] : bias_b[col - 1024];
            float bv1 = (col + 1 < 1024) ? bias_a[col + 1] : bias_b[col + 1 - 1024];
            *(__half2*)&C[(size_t)row * 2048 + col] =
                __floats2half2_rn(acc[mi][j][0] + bv0, acc[mi][j][1] + bv1);
            *(__half2*)&C[(size_t)(row + 8) * 2048 + col] =
                __floats2half2_rn(acc[mi][j][2] + bv0, acc[mi][j][3] + bv1);
        }
    }
}

// ---------------- fp16 mma skinny split-K (single A) ------------------------
#define SKSTG0 16384

__global__ __launch_bounds__(256) void mma_skinny1(
    const __half* __restrict__ A1, int lda1, int K1,
    const __half* __restrict__ Bw, int ldw, int NB,
    float* __restrict__ P1)
{
    extern __shared__ char smem[];
    const uint32_t sbase = smem_u32(smem);
    const int tid  = threadIdx.x;
    const int lane = tid & 31, wid = tid >> 5;
    const int wm = wid >> 1, wn = wid & 1;
    const int bmRow = (blockIdx.x / NB) * 64;
    const int bn    = (blockIdx.x % NB) * 64;

    const int total_tiles = K1 >> 6;
    const int per = (total_tiles + SPLITK - 1) / SPLITK;
    const int t0 = blockIdx.y * per;
    int t1 = t0 + per; if (t1 > total_tiles) t1 = total_tiles;

    float acc[4][4] = {};
    const int lrow = tid >> 2;
    const int lc0  = (tid & 3) * 2;
    uint32_t sw[2];
    #pragma unroll
    for (int i = 0; i < 2; i++)
        sw[i] = (uint32_t)lrow * 128 + (((lc0 + i) ^ (lrow & 7)) * 16);

    auto load_tile = [&](int t, int stg) {
        const int k0 = t << 6;
        uint32_t sA = sbase + stg * SKSTG0;
        uint32_t sB = sA + 8192;
        const __half* Arow = A1 + (size_t)(bmRow + lrow) * lda1 + k0;
        const __half* Brow = Bw + (size_t)(bn + lrow) * ldw + k0;
        #pragma unroll
        for (int i = 0; i < 2; i++) {
            CP_ASYNC16(sA + sw[i], Arow + (lc0 + i) * 8);
            CP_ASYNC16(sB + sw[i], Brow + (lc0 + i) * 8);
        }
        CP_COMMIT();
    };

    const int arow = (lane & 15);
    const int acol = (lane >> 4);
    const int brow = (lane & 7) + ((lane >> 4) << 3);
    const int bcol = (lane >> 3) & 1;

    if (t0 < t1) {
        load_tile(t0, t0 & 1);
        for (int t = t0; t < t1; t++) {
            if (t + 1 < t1) { load_tile(t + 1, (t + 1) & 1); CP_WAIT1(); }
            else            { CP_WAIT0(); }
            __syncthreads();
            uint32_t sA = sbase + (t & 1) * SKSTG0;
            uint32_t sB = sA + 8192;
            #pragma unroll
            for (int ks = 0; ks < 4; ks++) {
                uint32_t af[4], bf[2][4];
                {
                    int r = wm * 16 + arow;
                    int c = 2 * ks + acol;
                    uint32_t addr = sA + r * 128 + ((c ^ (r & 7)) * 16);
                    LDMX4(af[0], af[1], af[2], af[3], addr);
                }
                #pragma unroll
                for (int bi = 0; bi < 2; bi++) {
                    int r = wn * 32 + bi * 16 + brow;
                    int c = 2 * ks + bcol;
                    uint32_t addr = sB + r * 128 + ((c ^ (r & 7)) * 16);
                    LDMX4(bf[bi][0], bf[bi][1], bf[bi][2], bf[bi][3], addr);
                }
                #pragma unroll
                for (int j = 0; j < 4; j++)
                    MMA16(acc[j], af, bf[j >> 1][(j & 1) * 2],
                          bf[j >> 1][(j & 1) * 2 + 1]);
            }
            __syncthreads();
        }
    }

    const int pw = NB * 64;
    #pragma unroll
    for (int j = 0; j < 4; j++) {
        int row = bmRow + wm * 16 + (lane >> 2);
        int col = bn + wn * 32 + j * 8 + (lane & 3) * 2;
        size_t base = ((size_t)blockIdx.y * BATCH + row) * pw + col;
        *(float2*)&P1[base]          = make_float2(acc[j][0], acc[j][1]);
        *(float2*)&P1[base + 8 * pw] = make_float2(acc[j][2], acc[j][3]);
    }
}

// ---------------- combined skinny: dual + wea + wout (4 partitions) ---------
#define SKSTG1 24576
#define NBLK_M (BATCH / 64)    // 32

__global__ __launch_bounds__(256) void mma_skinny_comb(
    const __half* __restrict__ readw, const __half* __restrict__ rw,
    const __half* __restrict__ memT,
    const __half* __restrict__ ht16, const __half* __restrict__ wea,
    const __half* __restrict__ wout,
    float* __restrict__ P1, float* __restrict__ P2,
    float* __restrict__ P3, float* __restrict__ P4)
{
    extern __shared__ char smem[];
    const uint32_t sbase = smem_u32(smem);
    const int tid  = threadIdx.x;
    const int lane = tid & 31, wid = tid >> 5;
    const int wm = wid >> 1, wn = wid & 1;

    const int bx = blockIdx.x;
    const bool dualp = bx < NBLK_M;
    const __half *A1, *A1d = nullptr, *Bw;
    float *Pout1, *Pout2 = nullptr;
    int lda, K, ldw, NB, bxe;
    if (dualp) {
        A1 = readw; A1d = rw; lda = MEMN; K = MEMN;
        Bw = memT; ldw = MEMN; NB = 1; bxe = bx;
        Pout1 = P1; Pout2 = P2;
    } else if (bx < 3 * NBLK_M) {
        A1 = ht16; lda = CTRLN; K = CTRLN;
        Bw = wea; ldw = CTRLN; NB = 2; bxe = bx - NBLK_M;
        Pout1 = P3;
    } else {
        A1 = ht16; lda = CTRLN; K = CTRLN;
        Bw = wout; ldw = CTRLN + VDIM; NB = 1; bxe = bx - 3 * NBLK_M;
        Pout1 = P4;
    }
    const int bmRow = (bxe / NB) * 64;
    const int bn    = (bxe % NB) * 64;

    const int total_tiles = K >> 6;
    const int per = (total_tiles + SPLITK - 1) / SPLITK;
    const int t0 = blockIdx.y * per;
    int t1 = t0 + per; if (t1 > total_tiles) t1 = total_tiles;

    float acc[4][4] = {};
    float accd[4][4] = {};
    const int lrow = tid >> 2;
    const int lc0  = (tid & 3) * 2;
    uint32_t sw[2];
    #pragma unroll
    for (int i = 0; i < 2; i++)
        sw[i] = (uint32_t)lrow * 128 + (((lc0 + i) ^ (lrow & 7)) * 16);

    auto load_tile = [&](int t, int stg) {
        int k0 = t << 6;
        uint32_t sA  = sbase + stg * SKSTG1;
        uint32_t sAd = sA + 8192;
        uint32_t sB  = sA + 16384;
        const __half* Arow = A1 + (size_t)(bmRow + lrow) * lda + k0;
        const __half* Brow = Bw + (size_t)(bn + lrow) * ldw + k0;
        #pragma unroll
        for (int i = 0; i < 2; i++) {
            CP_ASYNC16(sA + sw[i], Arow + (lc0 + i) * 8);
            CP_ASYNC16(sB + sw[i], Brow + (lc0 + i) * 8);
            if (dualp) {
                const __half* Adrow = A1d + (size_t)(bmRow + lrow) * lda + k0;
                CP_ASYNC16(sAd + sw[i], Adrow + (lc0 + i) * 8);
            }
        }
        CP_COMMIT();
    };

    const int arow = (lane & 15);
    const int acol = (lane >> 4);
    const int brow = (lane & 7) + ((lane >> 4) << 3);
    const int bcol = (lane >> 3) & 1;

    if (t0 < t1) {
        load_tile(t0, t0 & 1);
        for (int t = t0; t < t1; t++) {
            if (t + 1 < t1) { load_tile(t + 1, (t + 1) & 1); CP_WAIT1(); }
            else            { CP_WAIT0(); }
            __syncthreads();
            uint32_t sA  = sbase + (t & 1) * SKSTG1;
            uint32_t sAd = sA + 8192;
            uint32_t sB  = sA + 16384;
            #pragma unroll
            for (int ks = 0; ks < 4; ks++) {
                uint32_t af[4], afd[4], bf[2][4];
                {
                    int r = wm * 16 + arow;
                    int c = 2 * ks + acol;
                    uint32_t addr = sA + r * 128 + ((c ^ (r & 7)) * 16);
                    LDMX4(af[0], af[1], af[2], af[3], addr);
                    if (dualp) {
                        uint32_t addrd = sAd + r * 128 + ((c ^ (r & 7)) * 16);
                        LDMX4(afd[0], afd[1], afd[2], afd[3], addrd);
                    }
                }
                #pragma unroll
                for (int bi = 0; bi < 2; bi++) {
                    int r = wn * 32 + bi * 16 + brow;
                    int c = 2 * ks + bcol;
                    uint32_t addr = sB + r * 128 + ((c ^ (r & 7)) * 16);
                    LDMX4(bf[bi][0], bf[bi][1], bf[bi][2], bf[bi][3], addr);
                }
                #pragma unroll
                for (int j = 0; j < 4; j++) {
                    MMA16(acc[j], af, bf[j >> 1][(j & 1) * 2],
                          bf[j >> 1][(j & 1) * 2 + 1]);
                    if (dualp)
                        MMA16(accd[j], afd, bf[j >> 1][(j & 1) * 2],
                              bf[j >> 1][(j & 1) * 2 + 1]);
                }
            }
            __syncthreads();
        }
    }

    const int pw = NB * 64;
    #pragma unroll
    for (int j = 0; j < 4; j++) {
        int row = bmRow + wm * 16 + (lane >> 2);
        int col = bn + wn * 32 + j * 8 + (lane & 3) * 2;
        size_t base = ((size_t)blockIdx.y * BATCH + row) * pw + col;
        *(float2*)&Pout1[base]          = make_float2(acc[j][0], acc[j][1]);
        *(float2*)&Pout1[base + 8 * pw] = make_float2(acc[j][2], acc[j][3]);
        if (dualp) {
            *(float2*)&Pout2[base]          = make_float2(accd[j][0], accd[j][1]);
            *(float2*)&Pout2[base + 8 * pw] = make_float2(accd[j][2], accd[j][3]);
        }
    }
}

// ---------------- reduces ----------------------------------------------------
__global__ void reduce_act(const float* __restrict__ P,
                           __half* __restrict__ outh, int ldc, int coloff)
{
    int idx = blockIdx.x * blockDim.x + threadIdx.x;   // BATCH*16
    int r = idx >> 4, c = (idx & 15) * 4;
    float4 s = {0.f, 0.f, 0.f, 0.f};
    #pragma unroll
    for (int k = 0; k < SPLITK; k++) {
        float4 v = *(const float4*)&P[((size_t)k * BATCH + r) * 64 + c];
        s.x += v.x; s.y += v.y; s.z += v.z; s.w += v.w;
    }
    *(uint2*)&outh[(size_t)r * ldc + coloff + c] = h4(s);
}

// fused: rn = Σp1 - sig(Σp3e+be)*Σp2 + tanh(Σp3a+ba)*svec  (fp32, in smem)
//        out = Σp4 + b_out + rn @ wout_tail
__global__ void reduce_final(const float* __restrict__ P1,
                             const float* __restrict__ P2,
                             const float* __restrict__ P3,
                             const float* __restrict__ P4,
                             const float* __restrict__ b_erase,
                             const float* __restrict__ b_add,
                             const float* __restrict__ b_out,
                             const float* __restrict__ svec,
                             const __half* __restrict__ wout,
                             float* __restrict__ out)
{
    __shared__ float srn[16][68];
    const int tid = threadIdx.x;
    const int row = tid >> 4, c = (tid & 15) * 4;
    const int r = blockIdx.x * 16 + row;

    float4 s1 = {0.f, 0.f, 0.f, 0.f}, s2 = {0.f, 0.f, 0.f, 0.f};
    float4 se = {0.f, 0.f, 0.f, 0.f}, sa = {0.f, 0.f, 0.f, 0.f};
    float4 s4 = {0.f, 0.f, 0.f, 0.f};
    #pragma unroll
    for (int k = 0; k < SPLITK; k++) {
        float4 v = *(const float4*)&P1[((size_t)k * BATCH + r) * 64 + c];
        float4 u = *(const float4*)&P2[((size_t)k * BATCH + r) * 64 + c];
        float4 e = *(const float4*)&P3[((size_t)k * BATCH + r) * 128 + c];
        float4 a = *(const float4*)&P3[((size_t)k * BATCH + r) * 128 + 64 + c];
        float4 w = *(const float4*)&P4[((size_t)k * BATCH + r) * 64 + c];
        s1.x += v.x; s1.y += v.y; s1.z += v.z; s1.w += v.w;
        s2.x += u.x; s2.y += u.y; s2.z += u.z; s2.w += u.w;
        se.x += e.x; se.y += e.y; se.z += e.z; se.w += e.w;
        sa.x += a.x; sa.y += a.y; sa.z += a.z; sa.w += a.w;
        s4.x += w.x; s4.y += w.y; s4.z += w.z; s4.w += w.w;
    }
    float sv = svec[r];
    float ev[4] = {se.x, se.y, se.z, se.w};
    float av[4] = {sa.x, sa.y, sa.z, sa.w};
    float v1[4] = {s1.x, s1.y, s1.z, s1.w};
    float v2[4] = {s2.x, s2.y, s2.z, s2.w};
    #pragma unroll
    for (int q = 0; q < 4; q++) {
        float e = sigf(ev[q] + b_erase[c + q]);
        float a = tanf_(av[q] + b_add[c + q]);
        srn[row][c + q] = v1[q] - e * v2[q] + a * sv;
    }
    __syncthreads();

    float a0 = s4.x + b_out[c],     a1 = s4.y + b_out[c + 1];
    float a2 = s4.z + b_out[c + 2], a3 = s4.w + b_out[c + 3];
    const __half* w0 = wout + (size_t)(c + 0) * 576 + 512;
    const __half* w1 = wout + (size_t)(c + 1) * 576 + 512;
    const __half* w2 = wout + (size_t)(c + 2) * 576 + 512;
    const __half* w3 = wout + (size_t)(c + 3) * 576 + 512;
    #pragma unroll 16
    for (int v = 0; v < 64; v++) {
        float rv = srn[row][v];
        a0 += rv * __half2float(w0[v]);
        a1 += rv * __half2float(w1[v]);
        a2 += rv * __half2float(w2[v]);
        a3 += rv * __half2float(w3[v]);
    }
    *(float4*)&out[(size_t)r * 64 + c] = make_float4(a0, a1, a2, a3);
}

// ---------------- single merged pack kernel ----------------------------------
#define N_WCAT_F4  (2048 * 160)
#define N_WRW_F4   (2048 * 128)
#define N_WEAO_F4  25600
#define N_ACAT_F4  (BATCH * 144)
#define N_RWP_F4   (BATCH * 256)
#define N_ELEM_BLK ((N_WCAT_F4 + N_WRW_F4 + N_WEAO_F4 + N_ACAT_F4 + N_RWP_F4) / 256)
#define N_MEMT_BLK 64

__global__ void pack_all(const float* __restrict__ W_ih,
                         const float* __restrict__ W_hh,
                         const float* __restrict__ W_read,
                         const float* __restrict__ W_write,
                         const float* __restrict__ W_erase,
                         const float* __restrict__ W_add,
                         const float* __restrict__ W_out,
                         const float* __restrict__ x,
                         const float* __restrict__ h_prev,
                         const float* __restrict__ rwp,
                         const float* __restrict__ mem,
                         __half* __restrict__ wcat, __half* __restrict__ wrw,
                         __half* __restrict__ wea, __half* __restrict__ wout,
                         __half* __restrict__ acat, __half* __restrict__ rwph,
                         __half* __restrict__ memT)
{
    __shared__ float s[32][33];
    if (blockIdx.x >= N_ELEM_BLK) {
        int bxm = blockIdx.x - N_ELEM_BLK;
        int k0 = (bxm & 31) * 32, v0 = (bxm >> 5) * 32;
        int tx = threadIdx.x & 31, ty = threadIdx.x >> 5;
        #pragma unroll
        for (int i = 0; i < 4; i++)
            s[ty + i * 8][tx] = mem[(size_t)(k0 + ty + i * 8) * 64 + v0 + tx];
        __syncthreads();
        #pragma unroll
        for (int i = 0; i < 4; i++)
            memT[(size_t)(v0 + ty + i * 8) * MEMN + k0 + tx] =
                __float2half_rn(s[tx][ty + i * 8]);
        return;
    }
    int idx = blockIdx.x * 256 + threadIdx.x;
    if (idx < N_WCAT_F4) {
        int n = idx / 160, q = idx % 160;
        int orig = ((n >> 3) & 3) * 512 + ((n >> 5) << 3) + (n & 7);
        float4 v = (q < 32)
            ? *(const float4*)&W_ih[(size_t)orig * 128 + q * 4]
            : *(const float4*)&W_hh[(size_t)orig * 512 + (q - 32) * 4];
        *(uint2*)&wcat[(size_t)n * KCAT + q * 4] = h4(v);
        return;
    }
    idx -= N_WCAT_F4;
    if (idx < N_WRW_F4) {
        int n = idx >> 7, q = idx & 127;
        float4 v = (n < 1024)
            ? *(const float4*)&W_read[(size_t)n * 512 + q * 4]
            : *(const float4*)&W_write[(size_t)(n - 1024) * 512 + q * 4];
        *(uint2*)&wrw[(size_t)n * 512 + q * 4] = h4(v);
        return;
    }
    idx -= N_WRW_F4;
    if (idx < N_WEAO_F4) {
        if (idx < 16384) {
            int n = idx >> 7, q = idx & 127;
            float4 v = (n < 64)
                ? *(const float4*)&W_erase[(size_t)n * 512 + q * 4]
                : *(const float4*)&W_add[(size_t)(n - 64) * 512 + q * 4];
            *(uint2*)&wea[(size_t)n * 512 + q * 4] = h4(v);
        } else {
            int j = idx - 16384;
            float4 v = *(const float4*)&W_out[(size_t)j * 4];
            *(uint2*)&wout[(size_t)j * 4] = h4(v);
        }
        return;
    }
    idx -= N_WEAO_F4;
    if (idx < N_ACAT_F4) {
        int b = idx / 144, q = idx % 144;
        float4 v; int col;
        if (q < 16) { v = *(const float4*)&x[(size_t)b * 64 + q * 4]; col = q * 4; }
        else { v = *(const float4*)&h_prev[(size_t)b * 512 + (q - 16) * 4];
               col = 128 + (q - 16) * 4; }
        *(uint2*)&acat[(size_t)b * KCAT + col] = h4(v);
        return;
    }
    idx -= N_ACAT_F4;
    {
        float4 v = *(const float4*)&rwp[(size_t)idx * 4];
        *(uint2*)&rwph[(size_t)idx * 4] = h4(v);
    }
}

// ---------------- softmax -----------------------------------------------------
__device__ __forceinline__ float blk_reduce(float v, bool mx, float* sh)
{
    int lane = threadIdx.x & 31, wid = threadIdx.x >> 5;
    #pragma unroll
    for (int o = 16; o > 0; o >>= 1) {
        float t = __shfl_xor_sync(0xFFFFFFFFu, v, o);
        v = mx ? fmaxf(v, t) : (v + t);
    }
    if (lane == 0) sh[wid] = v;
    __syncthreads();
    if (wid == 0) {
        float r = (lane < 8) ? sh[lane] : (mx ? -1e30f : 0.f);
        #pragma unroll
        for (int o = 4; o > 0; o >>= 1) {
            float t = __shfl_xor_sync(0xFFFFFFFFu, r, o);
            r = mx ? fmaxf(r, t) : (r + t);
        }
        if (lane == 0) sh[0] = r;
    }
    __syncthreads();
    float r = sh[0];
    __syncthreads();
    return r;
}

__global__ void softmax_fuse_kernel(const __half* __restrict__ logits,
                                    __half* __restrict__ readw,
                                    __half* __restrict__ rwprod,
                                    float* __restrict__ svec)
{
    __shared__ float sh[8];
    int b = blockIdx.x;
    int t = threadIdx.x;
    const __half* r = logits + (size_t)b * 2048;
    const __half* w = r + 1024;
    float vr[4], vw[4];
    float mr = -1e30f, mw = -1e30f;
    #pragma unroll
    for (int i = 0; i < 4; i++) {
        vr[i] = __half2float(r[t + i * 256]);
        vw[i] = __half2float(w[t + i * 256]);
        mr = fmaxf(mr, vr[i]);  mw = fmaxf(mw, vw[i]);
    }
    mr = blk_reduce(mr, true, sh);
    mw = blk_reduce(mw, true, sh);
    float er[4], ew[4], sr = 0.f, sw = 0.f;
    #pragma unroll
    for (int i = 0; i < 4; i++) {
        er[i] = __expf(vr[i] - mr); sr += er[i];
        ew[i] = __expf(vw[i] - mw); sw += ew[i];
    }
    sr = blk_reduce(sr, false, sh);
    sw = blk_reduce(sw, false, sh);
    float inv_sr = __fdividef(1.0f, sr), inv_sw = __fdividef(1.0f, sw);
    float srw = 0.f;
    #pragma unroll
    for (int i = 0; i < 4; i++) {
        float a = er[i] * inv_sr;
        float p = a * (ew[i] * inv_sw);
        readw[(size_t)b * MEMN + t + i * 256] = __float2half_rn(a);
        rwprod[(size_t)b * MEMN + t + i * 256] = __float2half_rn(p);
        srw += p;
    }
    srw = blk_reduce(srw, false, sh);
    if (t == 0) svec[b] = srw;
}

// ---------------- launch ----------------------------------------------------
extern "C" void kernel_launch(void* const* d_in, const int* in_sizes, int n_in,
                              void* d_out, int out_size)
{
    const float* x       = (const float*)d_in[0];
    const float* h_prev  = (const float*)d_in[1];
    const float* c_prev  = (const float*)d_in[2];
    const float* rwp     = (const float*)d_in[3];
    const float* memory  = (const float*)d_in[4];
    const float* W_ih    = (const float*)d_in[5];
    const float* b_ih    = (const float*)d_in[6];
    const float* W_hh    = (const float*)d_in[7];
    const float* b_hh    = (const float*)d_in[8];
    const float* W_read  = (const float*)d_in[9];
    const float* b_read  = (const float*)d_in[10];
    const float* W_write = (const float*)d_in[11];
    const float* b_write = (const float*)d_in[12];
    const float* W_erase = (const float*)d_in[13];
    const float* b_erase = (const float*)d_in[14];
    const float* W_add   = (const float*)d_in[15];
    const float* b_add   = (const float*)d_in[16];
    const float* W_out   = (const float*)d_in[17];
    const float* b_out   = (const float*)d_in[18];
    float* out = (float*)d_out;

    __half *acat, *wcat, *wrw, *wea, *wout, *memT, *rwph, *ht16, *readw, *rw, *logits;
    float *svec, *p1, *p2, *p3, *p4;
    cudaGetSymbolAddress((void**)&acat,   g_acat);
    cudaGetSymbolAddress((void**)&wcat,   g_wcat);
    cudaGetSymbolAddress((void**)&wrw,    g_wrw);
    cudaGetSymbolAddress((void**)&wea,    g_wea);
    cudaGetSymbolAddress((void**)&wout,   g_wout);
    cudaGetSymbolAddress((void**)&memT,   g_memT);
    cudaGetSymbolAddress((void**)&rwph,   g_rwph);
    cudaGetSymbolAddress((void**)&logits, g_logits);
    cudaGetSymbolAddress((void**)&ht16,   g_ht16);
    cudaGetSymbolAddress((void**)&readw,  g_readw);
    cudaGetSymbolAddress((void**)&rw,     g_rw);
    cudaGetSymbolAddress((void**)&svec,   g_s);
    cudaGetSymbolAddress((void**)&p1,     g_p1);
    cudaGetSymbolAddress((void**)&p2,     g_p2);
    cudaGetSymbolAddress((void**)&p3,     g_p3);
    cudaGetSymbolAddress((void**)&p4,     g_p4);

    cudaFuncSetAttribute(mma_gates, cudaFuncAttributeMaxDynamicSharedMemorySize,
                         SMEM_MMA);
    cudaFuncSetAttribute(mma_logits, cudaFuncAttributeMaxDynamicSharedMemorySize,
                         SMEM_MMA);
    cudaFuncSetAttribute(mma_skinny1,
                         cudaFuncAttributeMaxDynamicSharedMemorySize, 2 * SKSTG0);
    cudaFuncSetAttribute(mma_skinny_comb,
                         cudaFuncAttributeMaxDynamicSharedMemorySize, 2 * SKSTG1);

    const int rgrid = (BATCH * 16) / 256;

    // 1) all packs in one launch
    pack_all<<<N_ELEM_BLK + N_MEMT_BLK, 256>>>(
        W_ih, W_hh, W_read, W_write, W_erase, W_add, W_out,
        x, h_prev, rwp, memory,
        wcat, wrw, wea, wout, acat, rwph, memT);

    // 2) read_prev = rwp @ memT^T -> acat[:, 64:128)
    mma_skinny1<<<dim3(NBLK_M, SPLITK), 256, 2 * SKSTG0>>>(
        rwph, MEMN, MEMN, memT, MEMN, 1, p1);
    reduce_act<<<rgrid, 256>>>(p1, acat, KCAT, 64);

    // 3) gates GEMM + fused LSTM -> ht16
    mma_gates<<<dim3(16, 16), 256, SMEM_MMA>>>(
        acat, wcat, KCAT, b_ih, b_hh, c_prev, ht16);

    // 4) logits = h @ [W_read;W_write]^T  (fp16 out)
    mma_logits<<<dim3(16, 16), 256, SMEM_MMA>>>(
        ht16, wrw, CTRLN, b_read, b_write, logits);

    // 5) softmaxes + row sums
    softmax_fuse_kernel<<<BATCH, 256>>>(logits, readw, rw, svec);

    // 6) combined skinny (4 partitions): dual + wea + wout-ht-phase
    mma_skinny_comb<<<dim3(4 * NBLK_M, SPLITK), 256, 2 * SKSTG1>>>(
        readw, rw, memT, ht16, wea, wout, p1, p2, p3, p4);

    // 7) fused final reduce: rn (in smem) + out GEMM tail
    reduce_final<<<rgrid, 256>>>(p1, p2, p3, p4,
                                 b_erase, b_add, b_out, svec, wout, out);
}

// round 14
// speedup vs baseline: 1.2212x; 1.1693x over previous
#include <cuda_runtime.h>
#include <cuda_fp16.h>
#include <math.h>
#include <stdint.h>

#define BATCH 2048
#define CTRLN 512
#define MEMN  1024
#define VDIM  64
#define KCAT  640
#define SPLITK 8

// ---------------- scratch (device globals: allocation-free) ----------------
__device__ __half g_acat[BATCH * KCAT];
__device__ __half g_wcat[2048 * KCAT];       // gate-interleaved [W_ih|W_hh]
__device__ __half g_wrw[2048 * CTRLN];
__device__ __half g_wea[128 * CTRLN];
__device__ __half g_wout[64 * (CTRLN + 64)];
__device__ __half g_memT[64 * MEMN];
__device__ __half g_rwph[BATCH * MEMN];
__device__ __half g_logits[BATCH * 2048];    // fp16 logits
__device__ __half g_ht16[BATCH * CTRLN];
__device__ __half g_readw[BATCH * MEMN];
__device__ __half g_rw[BATCH * MEMN];
__device__ float  g_s[BATCH];
__device__ __half g_readnew[BATCH * VDIM];
__device__ float  g_p1[SPLITK * BATCH * VDIM];
__device__ float  g_p2[SPLITK * BATCH * VDIM];
__device__ float  g_p3[SPLITK * BATCH * 128];

// ---------------- helpers ----------------------------------------------------
__device__ __forceinline__ uint32_t smem_u32(const void* p) {
    uint32_t a;
    asm("{ .reg .u64 t; cvta.to.shared.u64 t, %1; cvt.u32.u64 %0, t; }"
        : "=r"(a) : "l"(p));
    return a;
}
__device__ __forceinline__ uint2 h4(float4 v) {
    __half2 a = __floats2half2_rn(v.x, v.y);
    __half2 b = __floats2half2_rn(v.z, v.w);
    uint2 r;
    r.x = *(uint32_t*)&a;
    r.y = *(uint32_t*)&b;
    return r;
}
__device__ __forceinline__ float sigf(float x) {
    return __fdividef(1.0f, 1.0f + __expf(-x));
}
__device__ __forceinline__ float tanf_(float x) {
    float e = __expf(-2.0f * fabsf(x));
    float t = __fdividef(1.0f - e, 1.0f + e);
    return copysignf(t, x);
}

#define CP_ASYNC16(s, g) \
    asm volatile("cp.async.cg.shared.global [%0], [%1], 16;" \
                 :: "r"(s), "l"(g) : "memory")
#define CP_COMMIT() asm volatile("cp.async.commit_group;" ::: "memory")
#define CP_WAIT1()  asm volatile("cp.async.wait_group 1;" ::: "memory")
#define CP_WAIT0()  asm volatile("cp.async.wait_group 0;" ::: "memory")

#define LDMX4(r0, r1, r2, r3, a) \
    asm volatile("ldmatrix.sync.aligned.m8n8.x4.shared.b16 {%0,%1,%2,%3}, [%4];" \
                 : "=r"(r0), "=r"(r1), "=r"(r2), "=r"(r3) : "r"(a))

#define MMA16(d, a, b0, b1) \
    asm volatile("mma.sync.aligned.m16n8k16.row.col.f32.f16.f16.f32 " \
        "{%0,%1,%2,%3}, {%4,%5,%6,%7}, {%8,%9}, {%0,%1,%2,%3};" \
        : "+f"((d)[0]), "+f"((d)[1]), "+f"((d)[2]), "+f"((d)[3]) \
        : "r"((a)[0]), "r"((a)[1]), "r"((a)[2]), "r"((a)[3]), "r"(b0), "r"(b1))

// ---------------- fp16 big GEMM core: CTA 128x128, BK=64, 3 stages ----------
#define STAGE_SZ 32768
#define SMEM_MMA (3 * STAGE_SZ)

#define MMA_BIG_MAINLOOP(A, W, K)                                              \
    extern __shared__ char smem[];                                             \
    const int tid  = threadIdx.x;                                              \
    const int lane = tid & 31, wid = tid >> 5;                                 \
    const int wm = wid >> 2, wn = wid & 3;                                     \
    const int bm = blockIdx.y, bn = blockIdx.x;                                \
    const uint32_t sbase = smem_u32(smem);                                     \
    const int NT = (K) >> 6;                                                   \
    float acc[4][4][4] = {};                                                   \
    const int lrow = tid >> 1;                                                 \
    const int lc0  = (tid & 1) * 4;                                            \
    const __half* Ag = (A) + (size_t)(bm * 128 + lrow) * (K);                  \
    const __half* Wg = (W) + (size_t)(bn * 128 + lrow) * (K);                  \
    uint32_t sw[4];                                                            \
    _Pragma("unroll")                                                          \
    for (int i = 0; i < 4; i++)                                                \
        sw[i] = (uint32_t)lrow * 128 + (((lc0 + i) ^ (lrow & 7)) * 16);        \
    _Pragma("unroll")                                                          \
    for (int s = 0; s < 2; s++) {                                              \
        uint32_t sA = sbase + s * STAGE_SZ;                                    \
        uint32_t sB = sA + 16384;                                              \
        int k0 = s * 64;                                                       \
        _Pragma("unroll")                                                      \
        for (int i = 0; i < 4; i++) {                                          \
            CP_ASYNC16(sA + sw[i], Ag + k0 + (lc0 + i) * 8);                   \
            CP_ASYNC16(sB + sw[i], Wg + k0 + (lc0 + i) * 8);                   \
        }                                                                      \
        CP_COMMIT();                                                           \
    }                                                                          \
    const int arow = (lane & 15);                                              \
    const int acol = (lane >> 4);                                              \
    const int brow = (lane & 7) + ((lane >> 4) << 3);                          \
    const int bcol = (lane >> 3) & 1;                                          \
    for (int kt = 0; kt < NT; kt++) {                                          \
        CP_WAIT1();                                                            \
        __syncthreads();                                                       \
        if (kt + 2 < NT) {                                                     \
            int st = (kt + 2) % 3;                                             \
            uint32_t sA = sbase + st * STAGE_SZ;                               \
            uint32_t sB = sA + 16384;                                          \
            int k0 = (kt + 2) * 64;                                            \
            _Pragma("unroll")                                                  \
            for (int i = 0; i < 4; i++) {                                      \
                CP_ASYNC16(sA + sw[i], Ag + k0 + (lc0 + i) * 8);               \
                CP_ASYNC16(sB + sw[i], Wg + k0 + (lc0 + i) * 8);               \
            }                                                                  \
            CP_COMMIT();                                                       \
        }                                                                      \
        uint32_t sA = sbase + (kt % 3) * STAGE_SZ;                             \
        uint32_t sB = sA + 16384;                                              \
        _Pragma("unroll")                                                      \
        for (int ks = 0; ks < 4; ks++) {                                       \
            uint32_t af[4][4], bf[2][4];                                       \
            _Pragma("unroll")                                                  \
            for (int mi = 0; mi < 4; mi++) {                                   \
                int r = wm * 64 + mi * 16 + arow;                              \
                int c = 2 * ks + acol;                                         \
                uint32_t addr = sA + r * 128 + ((c ^ (r & 7)) * 16);           \
                LDMX4(af[mi][0], af[mi][1], af[mi][2], af[mi][3], addr);       \
            }                                                                  \
            _Pragma("unroll")                                                  \
            for (int bi = 0; bi < 2; bi++) {                                   \
                int r = wn * 32 + bi * 16 + brow;                              \
                int c = 2 * ks + bcol;                                         \
                uint32_t addr = sB + r * 128 + ((c ^ (r & 7)) * 16);           \
                LDMX4(bf[bi][0], bf[bi][1], bf[bi][2], bf[bi][3], addr);       \
            }                                                                  \
            _Pragma("unroll")                                                  \
            for (int mi = 0; mi < 4; mi++) {                                   \
                _Pragma("unroll")                                              \
                for (int j = 0; j < 4; j++)                                    \
                    MMA16(acc[mi][j], af[mi], bf[j >> 1][(j & 1) * 2],         \
                          bf[j >> 1][(j & 1) * 2 + 1]);                        \
            }                                                                  \
        }                                                                      \
    }

// ---------------- gates GEMM with fused LSTM epilogue ------------------------
__global__ __launch_bounds__(256, 2) void mma_gates(
    const __half* __restrict__ A, const __half* __restrict__ W, int K,
    const float* __restrict__ b_ih, const float* __restrict__ b_hh,
    const float* __restrict__ c_prev, __half* __restrict__ ht)
{
    MMA_BIG_MAINLOOP(A, W, K)

    const int q = lane & 3;
    const int u0 = (bn * 4 + wn) * 8 + q * 2;
    float bsum[4][2];
    #pragma unroll
    for (int j = 0; j < 4; j++)
        #pragma unroll
        for (int uu = 0; uu < 2; uu++) {
            int orig = j * 512 + u0 + uu;
            bsum[j][uu] = b_ih[orig] + b_hh[orig];
        }
    #pragma unroll
    for (int mi = 0; mi < 4; mi++) {
        int r0 = bm * 128 + wm * 64 + mi * 16 + (lane >> 2);
        #pragma unroll
        for (int rr = 0; rr < 2; rr++) {
            int r = r0 + rr * 8;
            float2 cp = *(const float2*)&c_prev[(size_t)r * 512 + u0];
            float cc[2] = {cp.x, cp.y};
            float hv[2];
            #pragma unroll
            for (int uu = 0; uu < 2; uu++) {
                int k = rr * 2 + uu;
                float gi = acc[mi][0][k] + bsum[0][uu];
                float gf = acc[mi][1][k] + bsum[1][uu];
                float gg = acc[mi][2][k] + bsum[2][uu];
                float go = acc[mi][3][k] + bsum[3][uu];
                float c = sigf(gf) * cc[uu] + sigf(gi) * tanf_(gg);
                hv[uu] = sigf(go) * tanf_(c);
            }
            *(__half2*)&ht[(size_t)r * 512 + u0] = __floats2half2_rn(hv[0], hv[1]);
        }
    }
}

// ---------------- logits GEMM (fp16 output, split bias) ----------------------
__global__ __launch_bounds__(256, 2) void mma_logits(
    const __half* __restrict__ A, const __half* __restrict__ W, int K,
    const float* __restrict__ bias_a, const float* __restrict__ bias_b,
    __half* __restrict__ C)
{
    MMA_BIG_MAINLOOP(A, W, K)

    #pragma unroll
    for (int mi = 0; mi < 4; mi++) {
        #pragma unroll
        for (int j = 0; j < 4; j++) {
            int row = bm * 128 + wm * 64 + mi * 16 + (lane >> 2);
            int col = bn * 128 + wn * 32 + j * 8 + (lane & 3) * 2;
            float bv0 = (col < 1024) ? bias_a[col] : bias_b[col - 1024];
            float bv1 = (col + 1 < 1024) ? bias_a[col + 1] : bias_b[col + 1 - 1024];
            *(__half2*)&C[(size_t)row * 2048 + col] =
                __floats2half2_rn(acc[mi][j][0] + bv0, acc[mi][j][1] + bv1);
            *(__half2*)&C[(size_t)(row + 8) * 2048 + col] =
                __floats2half2_rn(acc[mi][j][2] + bv0, acc[mi][j][3] + bv1);
        }
    }
}

// ---------------- fp16 mma skinny split-K (single/concat-A) -----------------
#define SKSTG0 16384

__global__ __launch_bounds__(256) void mma_skinny1(
    const __half* __restrict__ A1, int lda1, int K1,
    const __half* __restrict__ A2, int lda2, int K2,
    const __half* __restrict__ Bw, int ldw, int NB,
    float* __restrict__ P1)
{
    extern __shared__ char smem[];
    const uint32_t sbase = smem_u32(smem);
    const int tid  = threadIdx.x;
    const int lane = tid & 31, wid = tid >> 5;
    const int wm = wid >> 1, wn = wid & 1;
    const int bmRow = (blockIdx.x / NB) * 64;
    const int bn    = (blockIdx.x % NB) * 64;

    const int total_tiles = (K1 + K2) >> 6;
    const int per = (total_tiles + SPLITK - 1) / SPLITK;
    const int t0 = blockIdx.y * per;
    int t1 = t0 + per; if (t1 > total_tiles) t1 = total_tiles;
    const int nt1 = K1 >> 6;

    float acc[4][4] = {};
    const int lrow = tid >> 2;
    const int lc0  = (tid & 3) * 2;
    uint32_t sw[2];
    #pragma unroll
    for (int i = 0; i < 2; i++)
        sw[i] = (uint32_t)lrow * 128 + (((lc0 + i) ^ (lrow & 7)) * 16);

    auto load_tile = [&](int t, int stg) {
        const __half* Ag; int lda, kA;
        if (t < nt1) { Ag = A1; lda = lda1; kA = t << 6; }
        else         { Ag = A2; lda = lda2; kA = (t - nt1) << 6; }
        const int kB = t << 6;
        uint32_t sA = sbase + stg * SKSTG0;
        uint32_t sB = sA + 8192;
        const __half* Arow = Ag + (size_t)(bmRow + lrow) * lda + kA;
        const __half* Brow = Bw + (size_t)(bn + lrow) * ldw + kB;
        #pragma unroll
        for (int i = 0; i < 2; i++) {
            CP_ASYNC16(sA + sw[i], Arow + (lc0 + i) * 8);
            CP_ASYNC16(sB + sw[i], Brow + (lc0 + i) * 8);
        }
        CP_COMMIT();
    };

    const int arow = (lane & 15);
    const int acol = (lane >> 4);
    const int brow = (lane & 7) + ((lane >> 4) << 3);
    const int bcol = (lane >> 3) & 1;

    if (t0 < t1) {
        load_tile(t0, t0 & 1);
        for (int t = t0; t < t1; t++) {
            if (t + 1 < t1) { load_tile(t + 1, (t + 1) & 1); CP_WAIT1(); }
            else            { CP_WAIT0(); }
            __syncthreads();
            uint32_t sA = sbase + (t & 1) * SKSTG0;
            uint32_t sB = sA + 8192;
            #pragma unroll
            for (int ks = 0; ks < 4; ks++) {
                uint32_t af[4], bf[2][4];
                {
                    int r = wm * 16 + arow;
                    int c = 2 * ks + acol;
                    uint32_t addr = sA + r * 128 + ((c ^ (r & 7)) * 16);
                    LDMX4(af[0], af[1], af[2], af[3], addr);
                }
                #pragma unroll
                for (int bi = 0; bi < 2; bi++) {
                    int r = wn * 32 + bi * 16 + brow;
                    int c = 2 * ks + bcol;
                    uint32_t addr = sB + r * 128 + ((c ^ (r & 7)) * 16);
                    LDMX4(bf[bi][0], bf[bi][1], bf[bi][2], bf[bi][3], addr);
                }
                #pragma unroll
                for (int j = 0; j < 4; j++)
                    MMA16(acc[j], af, bf[j >> 1][(j & 1) * 2],
                          bf[j >> 1][(j & 1) * 2 + 1]);
            }
            __syncthreads();
        }
    }

    const int pw = NB * 64;
    #pragma unroll
    for (int j = 0; j < 4; j++) {
        int row = bmRow + wm * 16 + (lane >> 2);
        int col = bn + wn * 32 + j * 8 + (lane & 3) * 2;
        size_t base = ((size_t)blockIdx.y * BATCH + row) * pw + col;
        *(float2*)&P1[base]          = make_float2(acc[j][0], acc[j][1]);
        *(float2*)&P1[base + 8 * pw] = make_float2(acc[j][2], acc[j][3]);
    }
}

// ---------------- combined skinny: dual (readw,rw)@memT^T + ht@wea^T --------
#define SKSTG1 24576

__global__ __launch_bounds__(256) void mma_skinny_comb(
    const __half* __restrict__ readw, const __half* __restrict__ rw,
    const __half* __restrict__ memT,
    const __half* __restrict__ ht16, const __half* __restrict__ wea,
    float* __restrict__ P1, float* __restrict__ P2, float* __restrict__ P3)
{
    extern __shared__ char smem[];
    const uint32_t sbase = smem_u32(smem);
    const int tid  = threadIdx.x;
    const int lane = tid & 31, wid = tid >> 5;
    const int wm = wid >> 1, wn = wid & 1;

    const bool dualp = blockIdx.x < (BATCH / 64);
    const __half *A1, *A1d = nullptr, *Bw;
    float *Pout1, *Pout2 = nullptr;
    int lda, K, ldw, NB, bxe;
    if (dualp) {
        A1 = readw; A1d = rw; lda = MEMN; K = MEMN;
        Bw = memT; ldw = MEMN; NB = 1; bxe = blockIdx.x;
        Pout1 = P1; Pout2 = P2;
    } else {
        A1 = ht16; lda = CTRLN; K = CTRLN;
        Bw = wea; ldw = CTRLN; NB = 2; bxe = blockIdx.x - BATCH / 64;
        Pout1 = P3;
    }
    const int bmRow = (bxe / NB) * 64;
    const int bn    = (bxe % NB) * 64;

    const int total_tiles = K >> 6;
    const int per = (total_tiles + SPLITK - 1) / SPLITK;
    const int t0 = blockIdx.y * per;
    int t1 = t0 + per; if (t1 > total_tiles) t1 = total_tiles;

    float acc[4][4] = {};
    float accd[4][4] = {};
    const int lrow = tid >> 2;
    const int lc0  = (tid & 3) * 2;
    uint32_t sw[2];
    #pragma unroll
    for (int i = 0; i < 2; i++)
        sw[i] = (uint32_t)lrow * 128 + (((lc0 + i) ^ (lrow & 7)) * 16);

    auto load_tile = [&](int t, int stg) {
        int k0 = t << 6;
        uint32_t sA  = sbase + stg * SKSTG1;
        uint32_t sAd = sA + 8192;
        uint32_t sB  = sA + 16384;
        const __half* Arow = A1 + (size_t)(bmRow + lrow) * lda + k0;
        const __half* Brow = Bw + (size_t)(bn + lrow) * ldw + k0;
        #pragma unroll
        for (int i = 0; i < 2; i++) {
            CP_ASYNC16(sA + sw[i], Arow + (lc0 + i) * 8);
            CP_ASYNC16(sB + sw[i], Brow + (lc0 + i) * 8);
            if (dualp) {
                const __half* Adrow = A1d + (size_t)(bmRow + lrow) * lda + k0;
                CP_ASYNC16(sAd + sw[i], Adrow + (lc0 + i) * 8);
            }
        }
        CP_COMMIT();
    };

    const int arow = (lane & 15);
    const int acol = (lane >> 4);
    const int brow = (lane & 7) + ((lane >> 4) << 3);
    const int bcol = (lane >> 3) & 1;

    if (t0 < t1) {
        load_tile(t0, t0 & 1);
        for (int t = t0; t < t1; t++) {
            if (t + 1 < t1) { load_tile(t + 1, (t + 1) & 1); CP_WAIT1(); }
            else            { CP_WAIT0(); }
            __syncthreads();
            uint32_t sA  = sbase + (t & 1) * SKSTG1;
            uint32_t sAd = sA + 8192;
            uint32_t sB  = sA + 16384;
            #pragma unroll
            for (int ks = 0; ks < 4; ks++) {
                uint32_t af[4], afd[4], bf[2][4];
                {
                    int r = wm * 16 + arow;
                    int c = 2 * ks + acol;
                    uint32_t addr = sA + r * 128 + ((c ^ (r & 7)) * 16);
                    LDMX4(af[0], af[1], af[2], af[3], addr);
                    if (dualp) {
                        uint32_t addrd = sAd + r * 128 + ((c ^ (r & 7)) * 16);
                        LDMX4(afd[0], afd[1], afd[2], afd[3], addrd);
                    }
                }
                #pragma unroll
                for (int bi = 0; bi < 2; bi++) {
                    int r = wn * 32 + bi * 16 + brow;
                    int c = 2 * ks + bcol;
                    uint32_t addr = sB + r * 128 + ((c ^ (r & 7)) * 16);
                    LDMX4(bf[bi][0], bf[bi][1], bf[bi][2], bf[bi][3], addr);
                }
                #pragma unroll
                for (int j = 0; j < 4; j++) {
                    MMA16(acc[j], af, bf[j >> 1][(j & 1) * 2],
                          bf[j >> 1][(j & 1) * 2 + 1]);
                    if (dualp)
                        MMA16(accd[j], afd, bf[j >> 1][(j & 1) * 2],
                              bf[j >> 1][(j & 1) * 2 + 1]);
                }
            }
            __syncthreads();
        }
    }

    const int pw = NB * 64;
    #pragma unroll
    for (int j = 0; j < 4; j++) {
        int row = bmRow + wm * 16 + (lane >> 2);
        int col = bn + wn * 32 + j * 8 + (lane & 3) * 2;
        size_t base = ((size_t)blockIdx.y * BATCH + row) * pw + col;
        *(float2*)&Pout1[base]          = make_float2(acc[j][0], acc[j][1]);
        *(float2*)&Pout1[base + 8 * pw] = make_float2(acc[j][2], acc[j][3]);
        if (dualp) {
            *(float2*)&Pout2[base]          = make_float2(accd[j][0], accd[j][1]);
            *(float2*)&Pout2[base + 8 * pw] = make_float2(accd[j][2], accd[j][3]);
        }
    }
}

// ---------------- reduces ----------------------------------------------------
__global__ void reduce_act(const float* __restrict__ P,
                           const float* __restrict__ bias,
                           int mode,
                           float* __restrict__ outf, __half* __restrict__ outh,
                           int ldc, int coloff)
{
    int idx = blockIdx.x * blockDim.x + threadIdx.x;   // BATCH*16
    int r = idx >> 4, c = (idx & 15) * 4;
    float4 s = {0.f, 0.f, 0.f, 0.f};
    #pragma unroll
    for (int k = 0; k < SPLITK; k++) {
        float4 v = *(const float4*)&P[((size_t)k * BATCH + r) * 64 + c];
        s.x += v.x; s.y += v.y; s.z += v.z; s.w += v.w;
    }
    if (bias) {
        s.x += bias[c]; s.y += bias[c + 1]; s.z += bias[c + 2]; s.w += bias[c + 3];
    }
    if (mode == 0) {
        *(float4*)&outf[(size_t)r * ldc + coloff + c] = s;
    } else {
        *(uint2*)&outh[(size_t)r * ldc + coloff + c] = h4(s);
    }
}

__global__ void reduce_readnew(const float* __restrict__ PA,
                               const float* __restrict__ PB,
                               const float* __restrict__ PE,
                               const float* __restrict__ b_erase,
                               const float* __restrict__ b_add,
                               const float* __restrict__ svec,
                               __half* __restrict__ rn)
{
    int idx = blockIdx.x * blockDim.x + threadIdx.x;   // BATCH*16
    int r = idx >> 4, c = (idx & 15) * 4;
    float4 s1 = {0.f, 0.f, 0.f, 0.f}, s2 = {0.f, 0.f, 0.f, 0.f};
    float4 se = {0.f, 0.f, 0.f, 0.f}, sa = {0.f, 0.f, 0.f, 0.f};
    #pragma unroll
    for (int k = 0; k < SPLITK; k++) {
        float4 v = *(const float4*)&PA[((size_t)k * BATCH + r) * 64 + c];
        float4 u = *(const float4*)&PB[((size_t)k * BATCH + r) * 64 + c];
        float4 e = *(const float4*)&PE[((size_t)k * BATCH + r) * 128 + c];
        float4 a = *(const float4*)&PE[((size_t)k * BATCH + r) * 128 + 64 + c];
        s1.x += v.x; s1.y += v.y; s1.z += v.z; s1.w += v.w;
        s2.x += u.x; s2.y += u.y; s2.z += u.z; s2.w += u.w;
        se.x += e.x; se.y += e.y; se.z += e.z; se.w += e.w;
        sa.x += a.x; sa.y += a.y; sa.z += a.z; sa.w += a.w;
    }
    float sv = svec[r];
    float ev[4] = {se.x, se.y, se.z, se.w};
    float av[4] = {sa.x, sa.y, sa.z, sa.w};
    float v1[4] = {s1.x, s1.y, s1.z, s1.w};
    float v2[4] = {s2.x, s2.y, s2.z, s2.w};
    float4 o;
    float* op = &o.x;
    #pragma unroll
    for (int q = 0; q < 4; q++) {
        float e = sigf(ev[q] + b_erase[c + q]);
        float a = tanf_(av[q] + b_add[c + q]);
        op[q] = v1[q] - e * v2[q] + a * sv;
    }
    *(uint2*)&rn[(size_t)r * 64 + c] = h4(o);
}

// ---------------- single merged pack kernel ----------------------------------
#define N_WCAT_F4  (2048 * 160)
#define N_WRW_F4   (2048 * 128)
#define N_WEAO_F4  25600
#define N_ACAT_F4  (BATCH * 144)
#define N_RWP_F4   (BATCH * 256)
#define N_ELEM_BLK ((N_WCAT_F4 + N_WRW_F4 + N_WEAO_F4 + N_ACAT_F4 + N_RWP_F4) / 256)
#define N_MEMT_BLK 64

__global__ void pack_all(const float* __restrict__ W_ih,
                         const float* __restrict__ W_hh,
                         const float* __restrict__ W_read,
                         const float* __restrict__ W_write,
                         const float* __restrict__ W_erase,
                         const float* __restrict__ W_add,
                         const float* __restrict__ W_out,
                         const float* __restrict__ x,
                         const float* __restrict__ h_prev,
                         const float* __restrict__ rwp,
                         const float* __restrict__ mem,
                         __half* __restrict__ wcat, __half* __restrict__ wrw,
                         __half* __restrict__ wea, __half* __restrict__ wout,
                         __half* __restrict__ acat, __half* __restrict__ rwph,
                         __half* __restrict__ memT)
{
    __shared__ float s[32][33];
    if (blockIdx.x >= N_ELEM_BLK) {
        int bxm = blockIdx.x - N_ELEM_BLK;
        int k0 = (bxm & 31) * 32, v0 = (bxm >> 5) * 32;
        int tx = threadIdx.x & 31, ty = threadIdx.x >> 5;
        #pragma unroll
        for (int i = 0; i < 4; i++)
            s[ty + i * 8][tx] = mem[(size_t)(k0 + ty + i * 8) * 64 + v0 + tx];
        __syncthreads();
        #pragma unroll
        for (int i = 0; i < 4; i++)
            memT[(size_t)(v0 + ty + i * 8) * MEMN + k0 + tx] =
                __float2half_rn(s[tx][ty + i * 8]);
        return;
    }
    int idx = blockIdx.x * 256 + threadIdx.x;
    if (idx < N_WCAT_F4) {
        int n = idx / 160, q = idx % 160;
        int orig = ((n >> 3) & 3) * 512 + ((n >> 5) << 3) + (n & 7);
        float4 v = (q < 32)
            ? *(const float4*)&W_ih[(size_t)orig * 128 + q * 4]
            : *(const float4*)&W_hh[(size_t)orig * 512 + (q - 32) * 4];
        *(uint2*)&wcat[(size_t)n * KCAT + q * 4] = h4(v);
        return;
    }
    idx -= N_WCAT_F4;
    if (idx < N_WRW_F4) {
        int n = idx >> 7, q = idx & 127;
        float4 v = (n < 1024)
            ? *(const float4*)&W_read[(size_t)n * 512 + q * 4]
            : *(const float4*)&W_write[(size_t)(n - 1024) * 512 + q * 4];
        *(uint2*)&wrw[(size_t)n * 512 + q * 4] = h4(v);
        return;
    }
    idx -= N_WRW_F4;
    if (idx < N_WEAO_F4) {
        if (idx < 16384) {
            int n = idx >> 7, q = idx & 127;
            float4 v = (n < 64)
                ? *(const float4*)&W_erase[(size_t)n * 512 + q * 4]
                : *(const float4*)&W_add[(size_t)(n - 64) * 512 + q * 4];
            *(uint2*)&wea[(size_t)n * 512 + q * 4] = h4(v);
        } else {
            int j = idx - 16384;
            float4 v = *(const float4*)&W_out[(size_t)j * 4];
            *(uint2*)&wout[(size_t)j * 4] = h4(v);
        }
        return;
    }
    idx -= N_WEAO_F4;
    if (idx < N_ACAT_F4) {
        int b = idx / 144, q = idx % 144;
        float4 v; int col;
        if (q < 16) { v = *(const float4*)&x[(size_t)b * 64 + q * 4]; col = q * 4; }
        else { v = *(const float4*)&h_prev[(size_t)b * 512 + (q - 16) * 4];
               col = 128 + (q - 16) * 4; }
        *(uint2*)&acat[(size_t)b * KCAT + col] = h4(v);
        return;
    }
    idx -= N_ACAT_F4;
    {
        float4 v = *(const float4*)&rwp[(size_t)idx * 4];
        *(uint2*)&rwph[(size_t)idx * 4] = h4(v);
    }
}

// ---------------- softmax (fp16 logits in) -----------------------------------
__device__ __forceinline__ float blk_reduce(float v, bool mx, float* sh)
{
    int lane = threadIdx.x & 31, wid = threadIdx.x >> 5;
    #pragma unroll
    for (int o = 16; o > 0; o >>= 1) {
        float t = __shfl_xor_sync(0xFFFFFFFFu, v, o);
        v = mx ? fmaxf(v, t) : (v + t);
    }
    if (lane == 0) sh[wid] = v;
    __syncthreads();
    if (wid == 0) {
        float r = (lane < 8) ? sh[lane] : (mx ? -1e30f : 0.f);
        #pragma unroll
        for (int o = 4; o > 0; o >>= 1) {
            float t = __shfl_xor_sync(0xFFFFFFFFu, r, o);
            r = mx ? fmaxf(r, t) : (r + t);
        }
        if (lane == 0) sh[0] = r;
    }
    __syncthreads();
    float r = sh[0];
    __syncthreads();
    return r;
}

__global__ void softmax_fuse_kernel(const __half* __restrict__ logits,
                                    __half* __restrict__ readw,
                                    __half* __restrict__ rwprod,
                                    float* __restrict__ svec)
{
    __shared__ float sh[8];
    int b = blockIdx.x;
    int t = threadIdx.x;
    const __half* r = logits + (size_t)b * 2048;
    const __half* w = r + 1024;
    float vr[4], vw[4];
    float mr = -1e30f, mw = -1e30f;
    #pragma unroll
    for (int i = 0; i < 4; i++) {
        vr[i] = __half2float(r[t + i * 256]);
        vw[i] = __half2float(w[t + i * 256]);
        mr = fmaxf(mr, vr[i]);  mw = fmaxf(mw, vw[i]);
    }
    mr = blk_reduce(mr, true, sh);
    mw = blk_reduce(mw, true, sh);
    float er[4], ew[4], sr = 0.f, sw = 0.f;
    #pragma unroll
    for (int i = 0; i < 4; i++) {
        er[i] = __expf(vr[i] - mr); sr += er[i];
        ew[i] = __expf(vw[i] - mw); sw += ew[i];
    }
    sr = blk_reduce(sr, false, sh);
    sw = blk_reduce(sw, false, sh);
    float inv_sr = __fdividef(1.0f, sr), inv_sw = __fdividef(1.0f, sw);
    float srw = 0.f;
    #pragma unroll
    for (int i = 0; i < 4; i++) {
        float a = er[i] * inv_sr;
        float p = a * (ew[i] * inv_sw);
        readw[(size_t)b * MEMN + t + i * 256] = __float2half_rn(a);
        rwprod[(size_t)b * MEMN + t + i * 256] = __float2half_rn(p);
        srw += p;
    }
    srw = blk_reduce(srw, false, sh);
    if (t == 0) svec[b] = srw;
}

// ---------------- launch ----------------------------------------------------
extern "C" void kernel_launch(void* const* d_in, const int* in_sizes, int n_in,
                              void* d_out, int out_size)
{
    const float* x       = (const float*)d_in[0];
    const float* h_prev  = (const float*)d_in[1];
    const float* c_prev  = (const float*)d_in[2];
    const float* rwp     = (const float*)d_in[3];
    const float* memory  = (const float*)d_in[4];
    const float* W_ih    = (const float*)d_in[5];
    const float* b_ih    = (const float*)d_in[6];
    const float* W_hh    = (const float*)d_in[7];
    const float* b_hh    = (const float*)d_in[8];
    const float* W_read  = (const float*)d_in[9];
    const float* b_read  = (const float*)d_in[10];
    const float* W_write = (const float*)d_in[11];
    const float* b_write = (const float*)d_in[12];
    const float* W_erase = (const float*)d_in[13];
    const float* b_erase = (const float*)d_in[14];
    const float* W_add   = (const float*)d_in[15];
    const float* b_add   = (const float*)d_in[16];
    const float* W_out   = (const float*)d_in[17];
    const float* b_out   = (const float*)d_in[18];
    float* out = (float*)d_out;

    __half *acat, *wcat, *wrw, *wea, *wout, *memT, *rwph, *ht16, *readw, *rw, *rn, *logits;
    float *svec, *p1, *p2, *p3;
    cudaGetSymbolAddress((void**)&acat,   g_acat);
    cudaGetSymbolAddress((void**)&wcat,   g_wcat);
    cudaGetSymbolAddress((void**)&wrw,    g_wrw);
    cudaGetSymbolAddress((void**)&wea,    g_wea);
    cudaGetSymbolAddress((void**)&wout,   g_wout);
    cudaGetSymbolAddress((void**)&memT,   g_memT);
    cudaGetSymbolAddress((void**)&rwph,   g_rwph);
    cudaGetSymbolAddress((void**)&logits, g_logits);
    cudaGetSymbolAddress((void**)&ht16,   g_ht16);
    cudaGetSymbolAddress((void**)&readw,  g_readw);
    cudaGetSymbolAddress((void**)&rw,     g_rw);
    cudaGetSymbolAddress((void**)&svec,   g_s);
    cudaGetSymbolAddress((void**)&rn,     g_readnew);
    cudaGetSymbolAddress((void**)&p1,     g_p1);
    cudaGetSymbolAddress((void**)&p2,     g_p2);
    cudaGetSymbolAddress((void**)&p3,     g_p3);

    cudaFuncSetAttribute(mma_gates, cudaFuncAttributeMaxDynamicSharedMemorySize,
                         SMEM_MMA);
    cudaFuncSetAttribute(mma_logits, cudaFuncAttributeMaxDynamicSharedMemorySize,
                         SMEM_MMA);
    cudaFuncSetAttribute(mma_skinny1,
                         cudaFuncAttributeMaxDynamicSharedMemorySize, 2 * SKSTG0);
    cudaFuncSetAttribute(mma_skinny_comb,
                         cudaFuncAttributeMaxDynamicSharedMemorySize, 2 * SKSTG1);

    const int rgrid = (BATCH * 16) / 256;

    // 1) all packs + rwp fp16 + memory transpose in ONE launch
    pack_all<<<N_ELEM_BLK + N_MEMT_BLK, 256>>>(
        W_ih, W_hh, W_read, W_write, W_erase, W_add, W_out,
        x, h_prev, rwp, memory,
        wcat, wrw, wea, wout, acat, rwph, memT);

    // 2) read_prev = rwp @ memT^T -> acat[:, 64:128)
    mma_skinny1<<<dim3(BATCH / 64, SPLITK), 256, 2 * SKSTG0>>>(
        rwph, MEMN, MEMN, nullptr, 0, 0, memT, MEMN, 1, p1);
    reduce_act<<<rgrid, 256>>>(p1, nullptr, 1, nullptr, acat, KCAT, 64);

    // 3) gates GEMM + fused LSTM -> ht16   (128x128 CTA)
    mma_gates<<<dim3(16, 16), 256, SMEM_MMA>>>(
        acat, wcat, KCAT, b_ih, b_hh, c_prev, ht16);

    // 4) logits = h @ [W_read;W_write]^T  (fp16 out)
    mma_logits<<<dim3(16, 16), 256, SMEM_MMA>>>(
        ht16, wrw, CTRLN, b_read, b_write, logits);

    // 5) softmaxes + row sums
    softmax_fuse_kernel<<<BATCH, 256>>>(logits, readw, rw, svec);

    // 6) combined skinny: dual (readw,rw)@memT^T + ht@[W_erase;W_add]^T
    mma_skinny_comb<<<dim3(3 * (BATCH / 64), SPLITK), 256, 2 * SKSTG1>>>(
        readw, rw, memT, ht16, wea, p1, p2, p3);

    // 7) fused reduce -> rn (fp16)
    reduce_readnew<<<rgrid, 256>>>(p1, p2, p3, b_erase, b_add, svec, rn);

    // 8) out = [h | rn] @ W_out^T + b_out
    mma_skinny1<<<dim3(BATCH / 64, SPLITK), 256, 2 * SKSTG0>>>(
        ht16, CTRLN, CTRLN, rn, VDIM, VDIM, wout, CTRLN + VDIM, 1, p1);
    reduce_act<<<rgrid, 256>>>(p1, b_out, 0, out, nullptr, 64, 0);
}

// round 15
// speedup vs baseline: 1.2477x; 1.0217x over previous
#include <cuda_runtime.h>
#include <cuda_fp16.h>
#include <math.h>
#include <stdint.h>

#define BATCH 2048
#define CTRLN 512
#define MEMN  1024
#define VDIM  64
#define KCAT  640
#define SPLITK 4

// ---------------- scratch (device globals: allocation-free) ----------------
__device__ __half g_acat[BATCH * KCAT];
__device__ __half g_wcat[2048 * KCAT];       // gate-interleaved [W_ih|W_hh]
__device__ __half g_wrw[2048 * CTRLN];
__device__ __half g_wea[128 * CTRLN];
__device__ __half g_wout[64 * (CTRLN + 64)];
__device__ __half g_memT[64 * MEMN];
__device__ __half g_rwph[BATCH * MEMN];
__device__ __half g_logits[BATCH * 2048];    // fp16 logits
__device__ __half g_ht16[BATCH * CTRLN];
__device__ __half g_readw[BATCH * MEMN];
__device__ __half g_rw[BATCH * MEMN];
__device__ float  g_s[BATCH];
__device__ __half g_readnew[BATCH * VDIM];
__device__ float  g_p1[SPLITK * BATCH * VDIM];
__device__ float  g_p2[SPLITK * BATCH * VDIM];
__device__ float  g_p3[SPLITK * BATCH * 128];

// ---------------- helpers ----------------------------------------------------
__device__ __forceinline__ uint32_t smem_u32(const void* p) {
    uint32_t a;
    asm("{ .reg .u64 t; cvta.to.shared.u64 t, %1; cvt.u32.u64 %0, t; }"
        : "=r"(a) : "l"(p));
    return a;
}
__device__ __forceinline__ uint2 h4(float4 v) {
    __half2 a = __floats2half2_rn(v.x, v.y);
    __half2 b = __floats2half2_rn(v.z, v.w);
    uint2 r;
    r.x = *(uint32_t*)&a;
    r.y = *(uint32_t*)&b;
    return r;
}
__device__ __forceinline__ float sigf(float x) {
    return __fdividef(1.0f, 1.0f + __expf(-x));
}
__device__ __forceinline__ float tanf_(float x) {
    float e = __expf(-2.0f * fabsf(x));
    float t = __fdividef(1.0f - e, 1.0f + e);
    return copysignf(t, x);
}

#define CP_ASYNC16(s, g) \
    asm volatile("cp.async.cg.shared.global [%0], [%1], 16;" \
                 :: "r"(s), "l"(g) : "memory")
#define CP_COMMIT() asm volatile("cp.async.commit_group;" ::: "memory")
#define CP_WAIT1()  asm volatile("cp.async.wait_group 1;" ::: "memory")
#define CP_WAIT0()  asm volatile("cp.async.wait_group 0;" ::: "memory")

#define LDMX4(r0, r1, r2, r3, a) \
    asm volatile("ldmatrix.sync.aligned.m8n8.x4.shared.b16 {%0,%1,%2,%3}, [%4];" \
                 : "=r"(r0), "=r"(r1), "=r"(r2), "=r"(r3) : "r"(a))

#define MMA16(d, a, b0, b1) \
    asm volatile("mma.sync.aligned.m16n8k16.row.col.f32.f16.f16.f32 " \
        "{%0,%1,%2,%3}, {%4,%5,%6,%7}, {%8,%9}, {%0,%1,%2,%3};" \
        : "+f"((d)[0]), "+f"((d)[1]), "+f"((d)[2]), "+f"((d)[3]) \
        : "r"((a)[0]), "r"((a)[1]), "r"((a)[2]), "r"((a)[3]), "r"(b0), "r"(b1))

// ---------------- fp16 big GEMM core: CTA 128x128, BK=64, 3 stages ----------
#define STAGE_SZ 32768
#define SMEM_MMA (3 * STAGE_SZ)

#define MMA_BIG_MAINLOOP(A, W, K)                                              \
    extern __shared__ char smem[];                                             \
    const int tid  = threadIdx.x;                                              \
    const int lane = tid & 31, wid = tid >> 5;                                 \
    const int wm = wid >> 2, wn = wid & 3;                                     \
    const int bm = blockIdx.y, bn = blockIdx.x;                                \
    const uint32_t sbase = smem_u32(smem);                                     \
    const int NT = (K) >> 6;                                                   \
    float acc[4][4][4] = {};                                                   \
    const int lrow = tid >> 1;                                                 \
    const int lc0  = (tid & 1) * 4;                                            \
    const __half* Ag = (A) + (size_t)(bm * 128 + lrow) * (K);                  \
    const __half* Wg = (W) + (size_t)(bn * 128 + lrow) * (K);                  \
    uint32_t sw[4];                                                            \
    _Pragma("unroll")                                                          \
    for (int i = 0; i < 4; i++)                                                \
        sw[i] = (uint32_t)lrow * 128 + (((lc0 + i) ^ (lrow & 7)) * 16);        \
    _Pragma("unroll")                                                          \
    for (int s = 0; s < 2; s++) {                                              \
        uint32_t sA = sbase + s * STAGE_SZ;                                    \
        uint32_t sB = sA + 16384;                                              \
        int k0 = s * 64;                                                       \
        _Pragma("unroll")                                                      \
        for (int i = 0; i < 4; i++) {                                          \
            CP_ASYNC16(sA + sw[i], Ag + k0 + (lc0 + i) * 8);                   \
            CP_ASYNC16(sB + sw[i], Wg + k0 + (lc0 + i) * 8);                   \
        }                                                                      \
        CP_COMMIT();                                                           \
    }                                                                          \
    const int arow = (lane & 15);                                              \
    const int acol = (lane >> 4);                                              \
    const int brow = (lane & 7) + ((lane >> 4) << 3);                          \
    const int bcol = (lane >> 3) & 1;                                          \
    for (int kt = 0; kt < NT; kt++) {                                          \
        CP_WAIT1();                                                            \
        __syncthreads();                                                       \
        if (kt + 2 < NT) {                                                     \
            int st = (kt + 2) % 3;                                             \
            uint32_t sA = sbase + st * STAGE_SZ;                               \
            uint32_t sB = sA + 16384;                                          \
            int k0 = (kt + 2) * 64;                                            \
            _Pragma("unroll")                                                  \
            for (int i = 0; i < 4; i++) {                                      \
                CP_ASYNC16(sA + sw[i], Ag + k0 + (lc0 + i) * 8);               \
                CP_ASYNC16(sB + sw[i], Wg + k0 + (lc0 + i) * 8);               \
            }                                                                  \
            CP_COMMIT();                                                       \
        }                                                                      \
        uint32_t sA = sbase + (kt % 3) * STAGE_SZ;                             \
        uint32_t sB = sA + 16384;                                              \
        _Pragma("unroll")                                                      \
        for (int ks = 0; ks < 4; ks++) {                                       \
            uint32_t af[4][4], bf[2][4];                                       \
            _Pragma("unroll")                                                  \
            for (int mi = 0; mi < 4; mi++) {                                   \
                int r = wm * 64 + mi * 16 + arow;                              \
                int c = 2 * ks + acol;                                         \
                uint32_t addr = sA + r * 128 + ((c ^ (r & 7)) * 16);           \
                LDMX4(af[mi][0], af[mi][1], af[mi][2], af[mi][3], addr);       \
            }                                                                  \
            _Pragma("unroll")                                                  \
            for (int bi = 0; bi < 2; bi++) {                                   \
                int r = wn * 32 + bi * 16 + brow;                              \
                int c = 2 * ks + bcol;                                         \
                uint32_t addr = sB + r * 128 + ((c ^ (r & 7)) * 16);           \
                LDMX4(bf[bi][0], bf[bi][1], bf[bi][2], bf[bi][3], addr);       \
            }                                                                  \
            _Pragma("unroll")                                                  \
            for (int mi = 0; mi < 4; mi++) {                                   \
                _Pragma("unroll")                                              \
                for (int j = 0; j < 4; j++)                                    \
                    MMA16(acc[mi][j], af[mi], bf[j >> 1][(j & 1) * 2],         \
                          bf[j >> 1][(j & 1) * 2 + 1]);                        \
            }                                                                  \
        }                                                                      \
    }

// ---------------- gates GEMM with fused LSTM epilogue ------------------------
__global__ __launch_bounds__(256, 2) void mma_gates(
    const __half* __restrict__ A, const __half* __restrict__ W, int K,
    const float* __restrict__ b_ih, const float* __restrict__ b_hh,
    const float* __restrict__ c_prev, __half* __restrict__ ht)
{
    MMA_BIG_MAINLOOP(A, W, K)

    const int q = lane & 3;
    const int u0 = (bn * 4 + wn) * 8 + q * 2;
    float bsum[4][2];
    #pragma unroll
    for (int j = 0; j < 4; j++)
        #pragma unroll
        for (int uu = 0; uu < 2; uu++) {
            int orig = j * 512 + u0 + uu;
            bsum[j][uu] = b_ih[orig] + b_hh[orig];
        }
    #pragma unroll
    for (int mi = 0; mi < 4; mi++) {
        int r0 = bm * 128 + wm * 64 + mi * 16 + (lane >> 2);
        #pragma unroll
        for (int rr = 0; rr < 2; rr++) {
            int r = r0 + rr * 8;
            float2 cp = *(const float2*)&c_prev[(size_t)r * 512 + u0];
            float cc[2] = {cp.x, cp.y};
            float hv[2];
            #pragma unroll
            for (int uu = 0; uu < 2; uu++) {
                int k = rr * 2 + uu;
                float gi = acc[mi][0][k] + bsum[0][uu];
                float gf = acc[mi][1][k] + bsum[1][uu];
                float gg = acc[mi][2][k] + bsum[2][uu];
                float go = acc[mi][3][k] + bsum[3][uu];
                float c = sigf(gf) * cc[uu] + sigf(gi) * tanf_(gg);
                hv[uu] = sigf(go) * tanf_(c);
            }
            *(__half2*)&ht[(size_t)r * 512 + u0] = __floats2half2_rn(hv[0], hv[1]);
        }
    }
}

// ---------------- logits GEMM (fp16 output, split bias) ----------------------
__global__ __launch_bounds__(256, 2) void mma_logits(
    const __half* __restrict__ A, const __half* __restrict__ W, int K,
    const float* __restrict__ bias_a, const float* __restrict__ bias_b,
    __half* __restrict__ C)
{
    MMA_BIG_MAINLOOP(A, W, K)

    #pragma unroll
    for (int mi = 0; mi < 4; mi++) {
        #pragma unroll
        for (int j = 0; j < 4; j++) {
            int row = bm * 128 + wm * 64 + mi * 16 + (lane >> 2);
            int col = bn * 128 + wn * 32 + j * 8 + (lane & 3) * 2;
            float bv0 = (col < 1024) ? bias_a[col] : bias_b[col - 1024];
            float bv1 = (col + 1 < 1024) ? bias_a[col + 1] : bias_b[col + 1 - 1024];
            *(__half2*)&C[(size_t)row * 2048 + col] =
                __floats2half2_rn(acc[mi][j][0] + bv0, acc[mi][j][1] + bv1);
            *(__half2*)&C[(size_t)(row + 8) * 2048 + col] =
                __floats2half2_rn(acc[mi][j][2] + bv0, acc[mi][j][3] + bv1);
        }
    }
}

// ---------------- fp16 mma skinny split-K (single/concat-A) -----------------
#define SKSTG0 16384

__global__ __launch_bounds__(256) void mma_skinny1(
    const __half* __restrict__ A1, int lda1, int K1,
    const __half* __restrict__ A2, int lda2, int K2,
    const __half* __restrict__ Bw, int ldw, int NB,
    float* __restrict__ P1)
{
    extern __shared__ char smem[];
    const uint32_t sbase = smem_u32(smem);
    const int tid  = threadIdx.x;
    const int lane = tid & 31, wid = tid >> 5;
    const int wm = wid >> 1, wn = wid & 1;
    const int bmRow = (blockIdx.x / NB) * 64;
    const int bn    = (blockIdx.x % NB) * 64;

    const int total_tiles = (K1 + K2) >> 6;
    const int per = (total_tiles + SPLITK - 1) / SPLITK;
    const int t0 = blockIdx.y * per;
    int t1 = t0 + per; if (t1 > total_tiles) t1 = total_tiles;
    const int nt1 = K1 >> 6;

    float acc[4][4] = {};
    const int lrow = tid >> 2;
    const int lc0  = (tid & 3) * 2;
    uint32_t sw[2];
    #pragma unroll
    for (int i = 0; i < 2; i++)
        sw[i] = (uint32_t)lrow * 128 + (((lc0 + i) ^ (lrow & 7)) * 16);

    auto load_tile = [&](int t, int stg) {
        const __half* Ag; int lda, kA;
        if (t < nt1) { Ag = A1; lda = lda1; kA = t << 6; }
        else         { Ag = A2; lda = lda2; kA = (t - nt1) << 6; }
        const int kB = t << 6;
        uint32_t sA = sbase + stg * SKSTG0;
        uint32_t sB = sA + 8192;
        const __half* Arow = Ag + (size_t)(bmRow + lrow) * lda + kA;
        const __half* Brow = Bw + (size_t)(bn + lrow) * ldw + kB;
        #pragma unroll
        for (int i = 0; i < 2; i++) {
            CP_ASYNC16(sA + sw[i], Arow + (lc0 + i) * 8);
            CP_ASYNC16(sB + sw[i], Brow + (lc0 + i) * 8);
        }
        CP_COMMIT();
    };

    const int arow = (lane & 15);
    const int acol = (lane >> 4);
    const int brow = (lane & 7) + ((lane >> 4) << 3);
    const int bcol = (lane >> 3) & 1;

    if (t0 < t1) {
        load_tile(t0, t0 & 1);
        for (int t = t0; t < t1; t++) {
            if (t + 1 < t1) { load_tile(t + 1, (t + 1) & 1); CP_WAIT1(); }
            else            { CP_WAIT0(); }
            __syncthreads();
            uint32_t sA = sbase + (t & 1) * SKSTG0;
            uint32_t sB = sA + 8192;
            #pragma unroll
            for (int ks = 0; ks < 4; ks++) {
                uint32_t af[4], bf[2][4];
                {
                    int r = wm * 16 + arow;
                    int c = 2 * ks + acol;
                    uint32_t addr = sA + r * 128 + ((c ^ (r & 7)) * 16);
                    LDMX4(af[0], af[1], af[2], af[3], addr);
                }
                #pragma unroll
                for (int bi = 0; bi < 2; bi++) {
                    int r = wn * 32 + bi * 16 + brow;
                    int c = 2 * ks + bcol;
                    uint32_t addr = sB + r * 128 + ((c ^ (r & 7)) * 16);
                    LDMX4(bf[bi][0], bf[bi][1], bf[bi][2], bf[bi][3], addr);
                }
                #pragma unroll
                for (int j = 0; j < 4; j++)
                    MMA16(acc[j], af, bf[j >> 1][(j & 1) * 2],
                          bf[j >> 1][(j & 1) * 2 + 1]);
            }
            __syncthreads();
        }
    }

    const int pw = NB * 64;
    #pragma unroll
    for (int j = 0; j < 4; j++) {
        int row = bmRow + wm * 16 + (lane >> 2);
        int col = bn + wn * 32 + j * 8 + (lane & 3) * 2;
        size_t base = ((size_t)blockIdx.y * BATCH + row) * pw + col;
        *(float2*)&P1[base]          = make_float2(acc[j][0], acc[j][1]);
        *(float2*)&P1[base + 8 * pw] = make_float2(acc[j][2], acc[j][3]);
    }
}

// ---------------- combined skinny: dual (readw,rw)@memT^T + ht@wea^T --------
#define SKSTG1 24576

__global__ __launch_bounds__(256) void mma_skinny_comb(
    const __half* __restrict__ readw, const __half* __restrict__ rw,
    const __half* __restrict__ memT,
    const __half* __restrict__ ht16, const __half* __restrict__ wea,
    float* __restrict__ P1, float* __restrict__ P2, float* __restrict__ P3)
{
    extern __shared__ char smem[];
    const uint32_t sbase = smem_u32(smem);
    const int tid  = threadIdx.x;
    const int lane = tid & 31, wid = tid >> 5;
    const int wm = wid >> 1, wn = wid & 1;

    const bool dualp = blockIdx.x < (BATCH / 64);
    const __half *A1, *A1d = nullptr, *Bw;
    float *Pout1, *Pout2 = nullptr;
    int lda, K, ldw, NB, bxe;
    if (dualp) {
        A1 = readw; A1d = rw; lda = MEMN; K = MEMN;
        Bw = memT; ldw = MEMN; NB = 1; bxe = blockIdx.x;
        Pout1 = P1; Pout2 = P2;
    } else {
        A1 = ht16; lda = CTRLN; K = CTRLN;
        Bw = wea; ldw = CTRLN; NB = 2; bxe = blockIdx.x - BATCH / 64;
        Pout1 = P3;
    }
    const int bmRow = (bxe / NB) * 64;
    const int bn    = (bxe % NB) * 64;

    const int total_tiles = K >> 6;
    const int per = (total_tiles + SPLITK - 1) / SPLITK;
    const int t0 = blockIdx.y * per;
    int t1 = t0 + per; if (t1 > total_tiles) t1 = total_tiles;

    float acc[4][4] = {};
    float accd[4][4] = {};
    const int lrow = tid >> 2;
    const int lc0  = (tid & 3) * 2;
    uint32_t sw[2];
    #pragma unroll
    for (int i = 0; i < 2; i++)
        sw[i] = (uint32_t)lrow * 128 + (((lc0 + i) ^ (lrow & 7)) * 16);

    auto load_tile = [&](int t, int stg) {
        int k0 = t << 6;
        uint32_t sA  = sbase + stg * SKSTG1;
        uint32_t sAd = sA + 8192;
        uint32_t sB  = sA + 16384;
        const __half* Arow = A1 + (size_t)(bmRow + lrow) * lda + k0;
        const __half* Brow = Bw + (size_t)(bn + lrow) * ldw + k0;
        #pragma unroll
        for (int i = 0; i < 2; i++) {
            CP_ASYNC16(sA + sw[i], Arow + (lc0 + i) * 8);
            CP_ASYNC16(sB + sw[i], Brow + (lc0 + i) * 8);
            if (dualp) {
                const __half* Adrow = A1d + (size_t)(bmRow + lrow) * lda + k0;
                CP_ASYNC16(sAd + sw[i], Adrow + (lc0 + i) * 8);
            }
        }
        CP_COMMIT();
    };

    const int arow = (lane & 15);
    const int acol = (lane >> 4);
    const int brow = (lane & 7) + ((lane >> 4) << 3);
    const int bcol = (lane >> 3) & 1;

    if (t0 < t1) {
        load_tile(t0, t0 & 1);
        for (int t = t0; t < t1; t++) {
            if (t + 1 < t1) { load_tile(t + 1, (t + 1) & 1); CP_WAIT1(); }
            else            { CP_WAIT0(); }
            __syncthreads();
            uint32_t sA  = sbase + (t & 1) * SKSTG1;
            uint32_t sAd = sA + 8192;
            uint32_t sB  = sA + 16384;
            #pragma unroll
            for (int ks = 0; ks < 4; ks++) {
                uint32_t af[4], afd[4], bf[2][4];
                {
                    int r = wm * 16 + arow;
                    int c = 2 * ks + acol;
                    uint32_t addr = sA + r * 128 + ((c ^ (r & 7)) * 16);
                    LDMX4(af[0], af[1], af[2], af[3], addr);
                    if (dualp) {
                        uint32_t addrd = sAd + r * 128 + ((c ^ (r & 7)) * 16);
                        LDMX4(afd[0], afd[1], afd[2], afd[3], addrd);
                    }
                }
                #pragma unroll
                for (int bi = 0; bi < 2; bi++) {
                    int r = wn * 32 + bi * 16 + brow;
                    int c = 2 * ks + bcol;
                    uint32_t addr = sB + r * 128 + ((c ^ (r & 7)) * 16);
                    LDMX4(bf[bi][0], bf[bi][1], bf[bi][2], bf[bi][3], addr);
                }
                #pragma unroll
                for (int j = 0; j < 4; j++) {
                    MMA16(acc[j], af, bf[j >> 1][(j & 1) * 2],
                          bf[j >> 1][(j & 1) * 2 + 1]);
                    if (dualp)
                        MMA16(accd[j], afd, bf[j >> 1][(j & 1) * 2],
                              bf[j >> 1][(j & 1) * 2 + 1]);
                }
            }
            __syncthreads();
        }
    }

    const int pw = NB * 64;
    #pragma unroll
    for (int j = 0; j < 4; j++) {
        int row = bmRow + wm * 16 + (lane >> 2);
        int col = bn + wn * 32 + j * 8 + (lane & 3) * 2;
        size_t base = ((size_t)blockIdx.y * BATCH + row) * pw + col;
        *(float2*)&Pout1[base]          = make_float2(acc[j][0], acc[j][1]);
        *(float2*)&Pout1[base + 8 * pw] = make_float2(acc[j][2], acc[j][3]);
        if (dualp) {
            *(float2*)&Pout2[base]          = make_float2(accd[j][0], accd[j][1]);
            *(float2*)&Pout2[base + 8 * pw] = make_float2(accd[j][2], accd[j][3]);
        }
    }
}

// ---------------- reduces ----------------------------------------------------
__global__ void reduce_act(const float* __restrict__ P,
                           const float* __restrict__ bias,
                           int mode,
                           float* __restrict__ outf, __half* __restrict__ outh,
                           int ldc, int coloff)
{
    int idx = blockIdx.x * blockDim.x + threadIdx.x;   // BATCH*16
    int r = idx >> 4, c = (idx & 15) * 4;
    float4 s = {0.f, 0.f, 0.f, 0.f};
    #pragma unroll
    for (int k = 0; k < SPLITK; k++) {
        float4 v = *(const float4*)&P[((size_t)k * BATCH + r) * 64 + c];
        s.x += v.x; s.y += v.y; s.z += v.z; s.w += v.w;
    }
    if (bias) {
        s.x += bias[c]; s.y += bias[c + 1]; s.z += bias[c + 2]; s.w += bias[c + 3];
    }
    if (mode == 0) {
        *(float4*)&outf[(size_t)r * ldc + coloff + c] = s;
    } else {
        *(uint2*)&outh[(size_t)r * ldc + coloff + c] = h4(s);
    }
}

__global__ void reduce_readnew(const float* __restrict__ PA,
                               const float* __restrict__ PB,
                               const float* __restrict__ PE,
                               const float* __restrict__ b_erase,
                               const float* __restrict__ b_add,
                               const float* __restrict__ svec,
                               __half* __restrict__ rn)
{
    int idx = blockIdx.x * blockDim.x + threadIdx.x;   // BATCH*16
    int r = idx >> 4, c = (idx & 15) * 4;
    float4 s1 = {0.f, 0.f, 0.f, 0.f}, s2 = {0.f, 0.f, 0.f, 0.f};
    float4 se = {0.f, 0.f, 0.f, 0.f}, sa = {0.f, 0.f, 0.f, 0.f};
    #pragma unroll
    for (int k = 0; k < SPLITK; k++) {
        float4 v = *(const float4*)&PA[((size_t)k * BATCH + r) * 64 + c];
        float4 u = *(const float4*)&PB[((size_t)k * BATCH + r) * 64 + c];
        float4 e = *(const float4*)&PE[((size_t)k * BATCH + r) * 128 + c];
        float4 a = *(const float4*)&PE[((size_t)k * BATCH + r) * 128 + 64 + c];
        s1.x += v.x; s1.y += v.y; s1.z += v.z; s1.w += v.w;
        s2.x += u.x; s2.y += u.y; s2.z += u.z; s2.w += u.w;
        se.x += e.x; se.y += e.y; se.z += e.z; se.w += e.w;
        sa.x += a.x; sa.y += a.y; sa.z += a.z; sa.w += a.w;
    }
    float sv = svec[r];
    float ev[4] = {se.x, se.y, se.z, se.w};
    float av[4] = {sa.x, sa.y, sa.z, sa.w};
    float v1[4] = {s1.x, s1.y, s1.z, s1.w};
    float v2[4] = {s2.x, s2.y, s2.z, s2.w};
    float4 o;
    float* op = &o.x;
    #pragma unroll
    for (int q = 0; q < 4; q++) {
        float e = sigf(ev[q] + b_erase[c + q]);
        float a = tanf_(av[q] + b_add[c + q]);
        op[q] = v1[q] - e * v2[q] + a * sv;
    }
    *(uint2*)&rn[(size_t)r * 64 + c] = h4(o);
}

// ---------------- single merged pack kernel ----------------------------------
#define N_WCAT_F4  (2048 * 160)
#define N_WRW_F4   (2048 * 128)
#define N_WEAO_F4  25600
#define N_ACAT_F4  (BATCH * 144)
#define N_RWP_F4   (BATCH * 256)
#define N_ELEM_BLK ((N_WCAT_F4 + N_WRW_F4 + N_WEAO_F4 + N_ACAT_F4 + N_RWP_F4) / 256)
#define N_MEMT_BLK 64

__global__ void pack_all(const float* __restrict__ W_ih,
                         const float* __restrict__ W_hh,
                         const float* __restrict__ W_read,
                         const float* __restrict__ W_write,
                         const float* __restrict__ W_erase,
                         const float* __restrict__ W_add,
                         const float* __restrict__ W_out,
                         const float* __restrict__ x,
                         const float* __restrict__ h_prev,
                         const float* __restrict__ rwp,
                         const float* __restrict__ mem,
                         __half* __restrict__ wcat, __half* __restrict__ wrw,
                         __half* __restrict__ wea, __half* __restrict__ wout,
                         __half* __restrict__ acat, __half* __restrict__ rwph,
                         __half* __restrict__ memT)
{
    __shared__ float s[32][33];
    if (blockIdx.x >= N_ELEM_BLK) {
        int bxm = blockIdx.x - N_ELEM_BLK;
        int k0 = (bxm & 31) * 32, v0 = (bxm >> 5) * 32;
        int tx = threadIdx.x & 31, ty = threadIdx.x >> 5;
        #pragma unroll
        for (int i = 0; i < 4; i++)
            s[ty + i * 8][tx] = mem[(size_t)(k0 + ty + i * 8) * 64 + v0 + tx];
        __syncthreads();
        #pragma unroll
        for (int i = 0; i < 4; i++)
            memT[(size_t)(v0 + ty + i * 8) * MEMN + k0 + tx] =
                __float2half_rn(s[tx][ty + i * 8]);
        return;
    }
    int idx = blockIdx.x * 256 + threadIdx.x;
    if (idx < N_WCAT_F4) {
        int n = idx / 160, q = idx % 160;
        int orig = ((n >> 3) & 3) * 512 + ((n >> 5) << 3) + (n & 7);
        float4 v = (q < 32)
            ? *(const float4*)&W_ih[(size_t)orig * 128 + q * 4]
            : *(const float4*)&W_hh[(size_t)orig * 512 + (q - 32) * 4];
        *(uint2*)&wcat[(size_t)n * KCAT + q * 4] = h4(v);
        return;
    }
    idx -= N_WCAT_F4;
    if (idx < N_WRW_F4) {
        int n = idx >> 7, q = idx & 127;
        float4 v = (n < 1024)
            ? *(const float4*)&W_read[(size_t)n * 512 + q * 4]
            : *(const float4*)&W_write[(size_t)(n - 1024) * 512 + q * 4];
        *(uint2*)&wrw[(size_t)n * 512 + q * 4] = h4(v);
        return;
    }
    idx -= N_WRW_F4;
    if (idx < N_WEAO_F4) {
        if (idx < 16384) {
            int n = idx >> 7, q = idx & 127;
            float4 v = (n < 64)
                ? *(const float4*)&W_erase[(size_t)n * 512 + q * 4]
                : *(const float4*)&W_add[(size_t)(n - 64) * 512 + q * 4];
            *(uint2*)&wea[(size_t)n * 512 + q * 4] = h4(v);
        } else {
            int j = idx - 16384;
            float4 v = *(const float4*)&W_out[(size_t)j * 4];
            *(uint2*)&wout[(size_t)j * 4] = h4(v);
        }
        return;
    }
    idx -= N_WEAO_F4;
    if (idx < N_ACAT_F4) {
        int b = idx / 144, q = idx % 144;
        float4 v; int col;
        if (q < 16) { v = *(const float4*)&x[(size_t)b * 64 + q * 4]; col = q * 4; }
        else { v = *(const float4*)&h_prev[(size_t)b * 512 + (q - 16) * 4];
               col = 128 + (q - 16) * 4; }
        *(uint2*)&acat[(size_t)b * KCAT + col] = h4(v);
        return;
    }
    idx -= N_ACAT_F4;
    {
        float4 v = *(const float4*)&rwp[(size_t)idx * 4];
        *(uint2*)&rwph[(size_t)idx * 4] = h4(v);
    }
}

// ---------------- softmax (fp16 logits in) -----------------------------------
__device__ __forceinline__ float blk_reduce(float v, bool mx, float* sh)
{
    int lane = threadIdx.x & 31, wid = threadIdx.x >> 5;
    #pragma unroll
    for (int o = 16; o > 0; o >>= 1) {
        float t = __shfl_xor_sync(0xFFFFFFFFu, v, o);
        v = mx ? fmaxf(v, t) : (v + t);
    }
    if (lane == 0) sh[wid] = v;
    __syncthreads();
    if (wid == 0) {
        float r = (lane < 8) ? sh[lane] : (mx ? -1e30f : 0.f);
        #pragma unroll
        for (int o = 4; o > 0; o >>= 1) {
            float t = __shfl_xor_sync(0xFFFFFFFFu, r, o);
            r = mx ? fmaxf(r, t) : (r + t);
        }
        if (lane == 0) sh[0] = r;
    }
    __syncthreads();
    float r = sh[0];
    __syncthreads();
    return r;
}

__global__ void softmax_fuse_kernel(const __half* __restrict__ logits,
                                    __half* __restrict__ readw,
                                    __half* __restrict__ rwprod,
                                    float* __restrict__ svec)
{
    __shared__ float sh[8];
    int b = blockIdx.x;
    int t = threadIdx.x;
    const __half* r = logits + (size_t)b * 2048;
    const __half* w = r + 1024;
    float vr[4], vw[4];
    float mr = -1e30f, mw = -1e30f;
    #pragma unroll
    for (int i = 0; i < 4; i++) {
        vr[i] = __half2float(r[t + i * 256]);
        vw[i] = __half2float(w[t + i * 256]);
        mr = fmaxf(mr, vr[i]);  mw = fmaxf(mw, vw[i]);
    }
    mr = blk_reduce(mr, true, sh);
    mw = blk_reduce(mw, true, sh);
    float er[4], ew[4], sr = 0.f, sw = 0.f;
    #pragma unroll
    for (int i = 0; i < 4; i++) {
        er[i] = __expf(vr[i] - mr); sr += er[i];
        ew[i] = __expf(vw[i] - mw); sw += ew[i];
    }
    sr = blk_reduce(sr, false, sh);
    sw = blk_reduce(sw, false, sh);
    float inv_sr = __fdividef(1.0f, sr), inv_sw = __fdividef(1.0f, sw);
    float srw = 0.f;
    #pragma unroll
    for (int i = 0; i < 4; i++) {
        float a = er[i] * inv_sr;
        float p = a * (ew[i] * inv_sw);
        readw[(size_t)b * MEMN + t + i * 256] = __float2half_rn(a);
        rwprod[(size_t)b * MEMN + t + i * 256] = __float2half_rn(p);
        srw += p;
    }
    srw = blk_reduce(srw, false, sh);
    if (t == 0) svec[b] = srw;
}

// ---------------- launch ----------------------------------------------------
extern "C" void kernel_launch(void* const* d_in, const int* in_sizes, int n_in,
                              void* d_out, int out_size)
{
    const float* x       = (const float*)d_in[0];
    const float* h_prev  = (const float*)d_in[1];
    const float* c_prev  = (const float*)d_in[2];
    const float* rwp     = (const float*)d_in[3];
    const float* memory  = (const float*)d_in[4];
    const float* W_ih    = (const float*)d_in[5];
    const float* b_ih    = (const float*)d_in[6];
    const float* W_hh    = (const float*)d_in[7];
    const float* b_hh    = (const float*)d_in[8];
    const float* W_read  = (const float*)d_in[9];
    const float* b_read  = (const float*)d_in[10];
    const float* W_write = (const float*)d_in[11];
    const float* b_write = (const float*)d_in[12];
    const float* W_erase = (const float*)d_in[13];
    const float* b_erase = (const float*)d_in[14];
    const float* W_add   = (const float*)d_in[15];
    const float* b_add   = (const float*)d_in[16];
    const float* W_out   = (const float*)d_in[17];
    const float* b_out   = (const float*)d_in[18];
    float* out = (float*)d_out;

    __half *acat, *wcat, *wrw, *wea, *wout, *memT, *rwph, *ht16, *readw, *rw, *rn, *logits;
    float *svec, *p1, *p2, *p3;
    cudaGetSymbolAddress((void**)&acat,   g_acat);
    cudaGetSymbolAddress((void**)&wcat,   g_wcat);
    cudaGetSymbolAddress((void**)&wrw,    g_wrw);
    cudaGetSymbolAddress((void**)&wea,    g_wea);
    cudaGetSymbolAddress((void**)&wout,   g_wout);
    cudaGetSymbolAddress((void**)&memT,   g_memT);
    cudaGetSymbolAddress((void**)&rwph,   g_rwph);
    cudaGetSymbolAddress((void**)&logits, g_logits);
    cudaGetSymbolAddress((void**)&ht16,   g_ht16);
    cudaGetSymbolAddress((void**)&readw,  g_readw);
    cudaGetSymbolAddress((void**)&rw,     g_rw);
    cudaGetSymbolAddress((void**)&svec,   g_s);
    cudaGetSymbolAddress((void**)&rn,     g_readnew);
    cudaGetSymbolAddress((void**)&p1,     g_p1);
    cudaGetSymbolAddress((void**)&p2,     g_p2);
    cudaGetSymbolAddress((void**)&p3,     g_p3);

    cudaFuncSetAttribute(mma_gates, cudaFuncAttributeMaxDynamicSharedMemorySize,
                         SMEM_MMA);
    cudaFuncSetAttribute(mma_logits, cudaFuncAttributeMaxDynamicSharedMemorySize,
                         SMEM_MMA);
    cudaFuncSetAttribute(mma_skinny1,
                         cudaFuncAttributeMaxDynamicSharedMemorySize, 2 * SKSTG0);
    cudaFuncSetAttribute(mma_skinny_comb,
                         cudaFuncAttributeMaxDynamicSharedMemorySize, 2 * SKSTG1);

    const int rgrid = (BATCH * 16) / 256;

    // 1) all packs + rwp fp16 + memory transpose in ONE launch
    pack_all<<<N_ELEM_BLK + N_MEMT_BLK, 256>>>(
        W_ih, W_hh, W_read, W_write, W_erase, W_add, W_out,
        x, h_prev, rwp, memory,
        wcat, wrw, wea, wout, acat, rwph, memT);

    // 2) read_prev = rwp @ memT^T -> acat[:, 64:128)
    mma_skinny1<<<dim3(BATCH / 64, SPLITK), 256, 2 * SKSTG0>>>(
        rwph, MEMN, MEMN, nullptr, 0, 0, memT, MEMN, 1, p1);
    reduce_act<<<rgrid, 256>>>(p1, nullptr, 1, nullptr, acat, KCAT, 64);

    // 3) gates GEMM + fused LSTM -> ht16   (128x128 CTA)
    mma_gates<<<dim3(16, 16), 256, SMEM_MMA>>>(
        acat, wcat, KCAT, b_ih, b_hh, c_prev, ht16);

    // 4) logits = h @ [W_read;W_write]^T  (fp16 out)
    mma_logits<<<dim3(16, 16), 256, SMEM_MMA>>>(
        ht16, wrw, CTRLN, b_read, b_write, logits);

    // 5) softmaxes + row sums
    softmax_fuse_kernel<<<BATCH, 256>>>(logits, readw, rw, svec);

    // 6) combined skinny: dual (readw,rw)@memT^T + ht@[W_erase;W_add]^T
    mma_skinny_comb<<<dim3(3 * (BATCH / 64), SPLITK), 256, 2 * SKSTG1>>>(
        readw, rw, memT, ht16, wea, p1, p2, p3);

    // 7) fused reduce -> rn (fp16)
    reduce_readnew<<<rgrid, 256>>>(p1, p2, p3, b_erase, b_add, svec, rn);

    // 8) out = [h | rn] @ W_out^T + b_out
    mma_skinny1<<<dim3(BATCH / 64, SPLITK), 256, 2 * SKSTG0>>>(
        ht16, CTRLN, CTRLN, rn, VDIM, VDIM, wout, CTRLN + VDIM, 1, p1);
    reduce_act<<<rgrid, 256>>>(p1, b_out, 0, out, nullptr, 64, 0);
}

// round 16
// speedup vs baseline: 1.2516x; 1.0031x over previous
#include <cuda_runtime.h>
#include <cuda_fp16.h>
#include <math.h>
#include <stdint.h>

#define BATCH 2048
#define CTRLN 512
#define MEMN  1024
#define VDIM  64
#define KCAT  640
#define SPLITK 4

// ---------------- scratch (device globals: allocation-free) ----------------
__device__ __half g_acat[BATCH * KCAT];
__device__ __half g_wcat[2048 * KCAT];       // gate-interleaved [W_ih|W_hh]
__device__ __half g_wrw[2048 * CTRLN];
__device__ __half g_wea[128 * CTRLN];
__device__ __half g_wout[64 * (CTRLN + 64)];
__device__ __half g_memT[64 * MEMN];
__device__ __half g_rwph[BATCH * MEMN];
__device__ __half g_logits[BATCH * 2048];
__device__ __half g_ht16[BATCH * CTRLN];
__device__ __half g_readw[BATCH * MEMN];
__device__ __half g_rw[BATCH * MEMN];
__device__ float  g_s[BATCH];
__device__ __half g_readnew[BATCH * VDIM];
__device__ float  g_p1[SPLITK * BATCH * VDIM];
__device__ float  g_p2[SPLITK * BATCH * VDIM];
__device__ float  g_p3[SPLITK * BATCH * 128];

// ---------------- helpers ----------------------------------------------------
__device__ __forceinline__ uint32_t smem_u32(const void* p) {
    uint32_t a;
    asm("{ .reg .u64 t; cvta.to.shared.u64 t, %1; cvt.u32.u64 %0, t; }"
        : "=r"(a) : "l"(p));
    return a;
}
__device__ __forceinline__ uint2 h4(float4 v) {
    __half2 a = __floats2half2_rn(v.x, v.y);
    __half2 b = __floats2half2_rn(v.z, v.w);
    uint2 r;
    r.x = *(uint32_t*)&a;
    r.y = *(uint32_t*)&b;
    return r;
}
__device__ __forceinline__ float sigf(float x) {
    return __fdividef(1.0f, 1.0f + __expf(-x));
}
__device__ __forceinline__ float tanf_(float x) {
    float e = __expf(-2.0f * fabsf(x));
    float t = __fdividef(1.0f - e, 1.0f + e);
    return copysignf(t, x);
}

#define CP_ASYNC16(s, g) \
    asm volatile("cp.async.cg.shared.global [%0], [%1], 16;" \
                 :: "r"(s), "l"(g) : "memory")
#define CP_COMMIT() asm volatile("cp.async.commit_group;" ::: "memory")
#define CP_WAIT2()  asm volatile("cp.async.wait_group 2;" ::: "memory")
#define CP_WAIT1()  asm volatile("cp.async.wait_group 1;" ::: "memory")
#define CP_WAIT0()  asm volatile("cp.async.wait_group 0;" ::: "memory")

// wait so that tile t is complete, given loads issued through min(t1-1, t+2)
#define CP_WAIT_TAIL(t, t1) do {                       \
    int _ia = ((t) + 2 < (t1) ? (t) + 2 : (t1) - 1) - (t); \
    if (_ia >= 2)      { CP_WAIT2(); }                 \
    else if (_ia == 1) { CP_WAIT1(); }                 \
    else               { CP_WAIT0(); }                 \
} while (0)

#define LDMX4(r0, r1, r2, r3, a) \
    asm volatile("ldmatrix.sync.aligned.m8n8.x4.shared.b16 {%0,%1,%2,%3}, [%4];" \
                 : "=r"(r0), "=r"(r1), "=r"(r2), "=r"(r3) : "r"(a))

#define MMA16(d, a, b0, b1) \
    asm volatile("mma.sync.aligned.m16n8k16.row.col.f32.f16.f16.f32 " \
        "{%0,%1,%2,%3}, {%4,%5,%6,%7}, {%8,%9}, {%0,%1,%2,%3};" \
        : "+f"((d)[0]), "+f"((d)[1]), "+f"((d)[2]), "+f"((d)[3]) \
        : "r"((a)[0]), "r"((a)[1]), "r"((a)[2]), "r"((a)[3]), "r"(b0), "r"(b1))

// ---------------- fp16 big GEMM core: CTA 128x128, BK=64, 3 stages ----------
#define STAGE_SZ 32768
#define SMEM_MMA (3 * STAGE_SZ)

#define MMA_BIG_MAINLOOP(A, W, K)                                              \
    extern __shared__ char smem[];                                             \
    const int tid  = threadIdx.x;                                              \
    const int lane = tid & 31, wid = tid >> 5;                                 \
    const int wm = wid >> 2, wn = wid & 3;                                     \
    const int bm = blockIdx.y, bn = blockIdx.x;                                \
    const uint32_t sbase = smem_u32(smem);                                     \
    const int NT = (K) >> 6;                                                   \
    float acc[4][4][4] = {};                                                   \
    const int lrow = tid >> 1;                                                 \
    const int lc0  = (tid & 1) * 4;                                            \
    const __half* Ag = (A) + (size_t)(bm * 128 + lrow) * (K);                  \
    const __half* Wg = (W) + (size_t)(bn * 128 + lrow) * (K);                  \
    uint32_t sw[4];                                                            \
    _Pragma("unroll")                                                          \
    for (int i = 0; i < 4; i++)                                                \
        sw[i] = (uint32_t)lrow * 128 + (((lc0 + i) ^ (lrow & 7)) * 16);        \
    _Pragma("unroll")                                                          \
    for (int s = 0; s < 2; s++) {                                              \
        uint32_t sA = sbase + s * STAGE_SZ;                                    \
        uint32_t sB = sA + 16384;                                              \
        int k0 = s * 64;                                                       \
        _Pragma("unroll")                                                      \
        for (int i = 0; i < 4; i++) {                                          \
            CP_ASYNC16(sA + sw[i], Ag + k0 + (lc0 + i) * 8);                   \
            CP_ASYNC16(sB + sw[i], Wg + k0 + (lc0 + i) * 8);                   \
        }                                                                      \
        CP_COMMIT();                                                           \
    }                                                                          \
    const int arow = (lane & 15);                                              \
    const int acol = (lane >> 4);                                              \
    const int brow = (lane & 7) + ((lane >> 4) << 3);                          \
    const int bcol = (lane >> 3) & 1;                                          \
    for (int kt = 0; kt < NT; kt++) {                                          \
        CP_WAIT1();                                                            \
        __syncthreads();                                                       \
        if (kt + 2 < NT) {                                                     \
            int st = (kt + 2) % 3;                                             \
            uint32_t sA = sbase + st * STAGE_SZ;                               \
            uint32_t sB = sA + 16384;                                          \
            int k0 = (kt + 2) * 64;                                            \
            _Pragma("unroll")                                                  \
            for (int i = 0; i < 4; i++) {                                      \
                CP_ASYNC16(sA + sw[i], Ag + k0 + (lc0 + i) * 8);               \
                CP_ASYNC16(sB + sw[i], Wg + k0 + (lc0 + i) * 8);               \
            }                                                                  \
            CP_COMMIT();                                                       \
        }                                                                      \
        uint32_t sA = sbase + (kt % 3) * STAGE_SZ;                             \
        uint32_t sB = sA + 16384;                                              \
        _Pragma("unroll")                                                      \
        for (int ks = 0; ks < 4; ks++) {                                       \
            uint32_t af[4][4], bf[2][4];                                       \
            _Pragma("unroll")                                                  \
            for (int mi = 0; mi < 4; mi++) {                                   \
                int r = wm * 64 + mi * 16 + arow;                              \
                int c = 2 * ks + acol;                                         \
                uint32_t addr = sA + r * 128 + ((c ^ (r & 7)) * 16);           \
                LDMX4(af[mi][0], af[mi][1], af[mi][2], af[mi][3], addr);       \
            }                                                                  \
            _Pragma("unroll")                                                  \
            for (int bi = 0; bi < 2; bi++) {                                   \
                int r = wn * 32 + bi * 16 + brow;                              \
                int c = 2 * ks + bcol;                                         \
                uint32_t addr = sB + r * 128 + ((c ^ (r & 7)) * 16);           \
                LDMX4(bf[bi][0], bf[bi][1], bf[bi][2], bf[bi][3], addr);       \
            }                                                                  \
            _Pragma("unroll")                                                  \
            for (int mi = 0; mi < 4; mi++) {                                   \
                _Pragma("unroll")                                              \
                for (int j = 0; j < 4; j++)                                    \
                    MMA16(acc[mi][j], af[mi], bf[j >> 1][(j & 1) * 2],         \
                          bf[j >> 1][(j & 1) * 2 + 1]);                        \
            }                                                                  \
        }                                                                      \
    }

// ---------------- gates GEMM with fused LSTM epilogue ------------------------
__global__ __launch_bounds__(256, 2) void mma_gates(
    const __half* __restrict__ A, const __half* __restrict__ W, int K,
    const float* __restrict__ b_ih, const float* __restrict__ b_hh,
    const float* __restrict__ c_prev, __half* __restrict__ ht)
{
    MMA_BIG_MAINLOOP(A, W, K)

    const int q = lane & 3;
    const int u0 = (bn * 4 + wn) * 8 + q * 2;
    float bsum[4][2];
    #pragma unroll
    for (int j = 0; j < 4; j++)
        #pragma unroll
        for (int uu = 0; uu < 2; uu++) {
            int orig = j * 512 + u0 + uu;
            bsum[j][uu] = b_ih[orig] + b_hh[orig];
        }
    #pragma unroll
    for (int mi = 0; mi < 4; mi++) {
        int r0 = bm * 128 + wm * 64 + mi * 16 + (lane >> 2);
        #pragma unroll
        for (int rr = 0; rr < 2; rr++) {
            int r = r0 + rr * 8;
            float2 cp = *(const float2*)&c_prev[(size_t)r * 512 + u0];
            float cc[2] = {cp.x, cp.y};
            float hv[2];
            #pragma unroll
            for (int uu = 0; uu < 2; uu++) {
                int k = rr * 2 + uu;
                float gi = acc[mi][0][k] + bsum[0][uu];
                float gf = acc[mi][1][k] + bsum[1][uu];
                float gg = acc[mi][2][k] + bsum[2][uu];
                float go = acc[mi][3][k] + bsum[3][uu];
                float c = sigf(gf) * cc[uu] + sigf(gi) * tanf_(gg);
                hv[uu] = sigf(go) * tanf_(c);
            }
            *(__half2*)&ht[(size_t)r * 512 + u0] = __floats2half2_rn(hv[0], hv[1]);
        }
    }
}

// ---------------- logits GEMM (fp16 output, split bias) ----------------------
__global__ __launch_bounds__(256, 2) void mma_logits(
    const __half* __restrict__ A, const __half* __restrict__ W, int K,
    const float* __restrict__ bias_a, const float* __restrict__ bias_b,
    __half* __restrict__ C)
{
    MMA_BIG_MAINLOOP(A, W, K)

    #pragma unroll
    for (int mi = 0; mi < 4; mi++) {
        #pragma unroll
        for (int j = 0; j < 4; j++) {
            int row = bm * 128 + wm * 64 + mi * 16 + (lane >> 2);
            int col = bn * 128 + wn * 32 + j * 8 + (lane & 3) * 2;
            float bv0 = (col < 1024) ? bias_a[col] : bias_b[col - 1024];
            float bv1 = (col + 1 < 1024) ? bias_a[col + 1] : bias_b[col + 1 - 1024];
            *(__half2*)&C[(size_t)row * 2048 + col] =
                __floats2half2_rn(acc[mi][j][0] + bv0, acc[mi][j][1] + bv1);
            *(__half2*)&C[(size_t)(row + 8) * 2048 + col] =
                __floats2half2_rn(acc[mi][j][2] + bv0, acc[mi][j][3] + bv1);
        }
    }
}

// ---------------- fp16 mma skinny split-K (single/concat-A), 3 stages -------
#define SKSTG0 16384

__global__ __launch_bounds__(256) void mma_skinny1(
    const __half* __restrict__ A1, int lda1, int K1,
    const __half* __restrict__ A2, int lda2, int K2,
    const __half* __restrict__ Bw, int ldw, int NB,
    float* __restrict__ P1)
{
    extern __shared__ char smem[];
    const uint32_t sbase = smem_u32(smem);
    const int tid  = threadIdx.x;
    const int lane = tid & 31, wid = tid >> 5;
    const int wm = wid >> 1, wn = wid & 1;
    const int bmRow = (blockIdx.x / NB) * 64;
    const int bn    = (blockIdx.x % NB) * 64;

    const int total_tiles = (K1 + K2) >> 6;
    const int per = (total_tiles + SPLITK - 1) / SPLITK;
    const int t0 = blockIdx.y * per;
    int t1 = t0 + per; if (t1 > total_tiles) t1 = total_tiles;
    const int nt1 = K1 >> 6;

    float acc[4][4] = {};
    const int lrow = tid >> 2;
    const int lc0  = (tid & 3) * 2;
    uint32_t sw[2];
    #pragma unroll
    for (int i = 0; i < 2; i++)
        sw[i] = (uint32_t)lrow * 128 + (((lc0 + i) ^ (lrow & 7)) * 16);

    auto load_tile = [&](int t, int stg) {
        const __half* Ag; int lda, kA;
        if (t < nt1) { Ag = A1; lda = lda1; kA = t << 6; }
        else         { Ag = A2; lda = lda2; kA = (t - nt1) << 6; }
        const int kB = t << 6;
        uint32_t sA = sbase + stg * SKSTG0;
        uint32_t sB = sA + 8192;
        const __half* Arow = Ag + (size_t)(bmRow + lrow) * lda + kA;
        const __half* Brow = Bw + (size_t)(bn + lrow) * ldw + kB;
        #pragma unroll
        for (int i = 0; i < 2; i++) {
            CP_ASYNC16(sA + sw[i], Arow + (lc0 + i) * 8);
            CP_ASYNC16(sB + sw[i], Brow + (lc0 + i) * 8);
        }
        CP_COMMIT();
    };

    const int arow = (lane & 15);
    const int acol = (lane >> 4);
    const int brow = (lane & 7) + ((lane >> 4) << 3);
    const int bcol = (lane >> 3) & 1;

    if (t0 < t1) {
        load_tile(t0, t0 % 3);
        if (t0 + 1 < t1) load_tile(t0 + 1, (t0 + 1) % 3);
        for (int t = t0; t < t1; t++) {
            if (t + 2 < t1) load_tile(t + 2, (t + 2) % 3);
            CP_WAIT_TAIL(t, t1);
            __syncthreads();
            uint32_t sA = sbase + (t % 3) * SKSTG0;
            uint32_t sB = sA + 8192;
            #pragma unroll
            for (int ks = 0; ks < 4; ks++) {
                uint32_t af[4], bf[2][4];
                {
                    int r = wm * 16 + arow;
                    int c = 2 * ks + acol;
                    uint32_t addr = sA + r * 128 + ((c ^ (r & 7)) * 16);
                    LDMX4(af[0], af[1], af[2], af[3], addr);
                }
                #pragma unroll
                for (int bi = 0; bi < 2; bi++) {
                    int r = wn * 32 + bi * 16 + brow;
                    int c = 2 * ks + bcol;
                    uint32_t addr = sB + r * 128 + ((c ^ (r & 7)) * 16);
                    LDMX4(bf[bi][0], bf[bi][1], bf[bi][2], bf[bi][3], addr);
                }
                #pragma unroll
                for (int j = 0; j < 4; j++)
                    MMA16(acc[j], af, bf[j >> 1][(j & 1) * 2],
                          bf[j >> 1][(j & 1) * 2 + 1]);
            }
            __syncthreads();
        }
    }

    const int pw = NB * 64;
    #pragma unroll
    for (int j = 0; j < 4; j++) {
        int row = bmRow + wm * 16 + (lane >> 2);
        int col = bn + wn * 32 + j * 8 + (lane & 3) * 2;
        size_t base = ((size_t)blockIdx.y * BATCH + row) * pw + col;
        *(float2*)&P1[base]          = make_float2(acc[j][0], acc[j][1]);
        *(float2*)&P1[base + 8 * pw] = make_float2(acc[j][2], acc[j][3]);
    }
}

// ---------------- combined skinny: dual + wea, 3 stages ----------------------
#define SKSTG1 24576

__global__ __launch_bounds__(256) void mma_skinny_comb(
    const __half* __restrict__ readw, const __half* __restrict__ rw,
    const __half* __restrict__ memT,
    const __half* __restrict__ ht16, const __half* __restrict__ wea,
    float* __restrict__ P1, float* __restrict__ P2, float* __restrict__ P3)
{
    extern __shared__ char smem[];
    const uint32_t sbase = smem_u32(smem);
    const int tid  = threadIdx.x;
    const int lane = tid & 31, wid = tid >> 5;
    const int wm = wid >> 1, wn = wid & 1;

    const bool dualp = blockIdx.x < (BATCH / 64);
    const __half *A1, *A1d = nullptr, *Bw;
    float *Pout1, *Pout2 = nullptr;
    int lda, K, ldw, NB, bxe;
    if (dualp) {
        A1 = readw; A1d = rw; lda = MEMN; K = MEMN;
        Bw = memT; ldw = MEMN; NB = 1; bxe = blockIdx.x;
        Pout1 = P1; Pout2 = P2;
    } else {
        A1 = ht16; lda = CTRLN; K = CTRLN;
        Bw = wea; ldw = CTRLN; NB = 2; bxe = blockIdx.x - BATCH / 64;
        Pout1 = P3;
    }
    const int bmRow = (bxe / NB) * 64;
    const int bn    = (bxe % NB) * 64;

    const int total_tiles = K >> 6;
    const int per = (total_tiles + SPLITK - 1) / SPLITK;
    const int t0 = blockIdx.y * per;
    int t1 = t0 + per; if (t1 > total_tiles) t1 = total_tiles;

    float acc[4][4] = {};
    float accd[4][4] = {};
    const int lrow = tid >> 2;
    const int lc0  = (tid & 3) * 2;
    uint32_t sw[2];
    #pragma unroll
    for (int i = 0; i < 2; i++)
        sw[i] = (uint32_t)lrow * 128 + (((lc0 + i) ^ (lrow & 7)) * 16);

    auto load_tile = [&](int t, int stg) {
        int k0 = t << 6;
        uint32_t sA  = sbase + stg * SKSTG1;
        uint32_t sAd = sA + 8192;
        uint32_t sB  = sA + 16384;
        const __half* Arow = A1 + (size_t)(bmRow + lrow) * lda + k0;
        const __half* Brow = Bw + (size_t)(bn + lrow) * ldw + k0;
        #pragma unroll
        for (int i = 0; i < 2; i++) {
            CP_ASYNC16(sA + sw[i], Arow + (lc0 + i) * 8);
            CP_ASYNC16(sB + sw[i], Brow + (lc0 + i) * 8);
            if (dualp) {
                const __half* Adrow = A1d + (size_t)(bmRow + lrow) * lda + k0;
                CP_ASYNC16(sAd + sw[i], Adrow + (lc0 + i) * 8);
            }
        }
        CP_COMMIT();
    };

    const int arow = (lane & 15);
    const int acol = (lane >> 4);
    const int brow = (lane & 7) + ((lane >> 4) << 3);
    const int bcol = (lane >> 3) & 1;

    if (t0 < t1) {
        load_tile(t0, t0 % 3);
        if (t0 + 1 < t1) load_tile(t0 + 1, (t0 + 1) % 3);
        for (int t = t0; t < t1; t++) {
            if (t + 2 < t1) load_tile(t + 2, (t + 2) % 3);
            CP_WAIT_TAIL(t, t1);
            __syncthreads();
            uint32_t sA  = sbase + (t % 3) * SKSTG1;
            uint32_t sAd = sA + 8192;
            uint32_t sB  = sA + 16384;
            #pragma unroll
            for (int ks = 0; ks < 4; ks++) {
                uint32_t af[4], afd[4], bf[2][4];
                {
                    int r = wm * 16 + arow;
                    int c = 2 * ks + acol;
                    uint32_t addr = sA + r * 128 + ((c ^ (r & 7)) * 16);
                    LDMX4(af[0], af[1], af[2], af[3], addr);
                    if (dualp) {
                        uint32_t addrd = sAd + r * 128 + ((c ^ (r & 7)) * 16);
                        LDMX4(afd[0], afd[1], afd[2], afd[3], addrd);
                    }
                }
                #pragma unroll
                for (int bi = 0; bi < 2; bi++) {
                    int r = wn * 32 + bi * 16 + brow;
                    int c = 2 * ks + bcol;
                    uint32_t addr = sB + r * 128 + ((c ^ (r & 7)) * 16);
                    LDMX4(bf[bi][0], bf[bi][1], bf[bi][2], bf[bi][3], addr);
                }
                #pragma unroll
                for (int j = 0; j < 4; j++) {
                    MMA16(acc[j], af, bf[j >> 1][(j & 1) * 2],
                          bf[j >> 1][(j & 1) * 2 + 1]);
                    if (dualp)
                        MMA16(accd[j], afd, bf[j >> 1][(j & 1) * 2],
                              bf[j >> 1][(j & 1) * 2 + 1]);
                }
            }
            __syncthreads();
        }
    }

    const int pw = NB * 64;
    #pragma unroll
    for (int j = 0; j < 4; j++) {
        int row = bmRow + wm * 16 + (lane >> 2);
        int col = bn + wn * 32 + j * 8 + (lane & 3) * 2;
        size_t base = ((size_t)blockIdx.y * BATCH + row) * pw + col;
        *(float2*)&Pout1[base]          = make_float2(acc[j][0], acc[j][1]);
        *(float2*)&Pout1[base + 8 * pw] = make_float2(acc[j][2], acc[j][3]);
        if (dualp) {
            *(float2*)&Pout2[base]          = make_float2(accd[j][0], accd[j][1]);
            *(float2*)&Pout2[base + 8 * pw] = make_float2(accd[j][2], accd[j][3]);
        }
    }
}

// ---------------- reduces ----------------------------------------------------
__global__ void reduce_act(const float* __restrict__ P,
                           const float* __restrict__ bias,
                           int mode,
                           float* __restrict__ outf, __half* __restrict__ outh,
                           int ldc, int coloff)
{
    int idx = blockIdx.x * blockDim.x + threadIdx.x;   // BATCH*16
    int r = idx >> 4, c = (idx & 15) * 4;
    float4 s = {0.f, 0.f, 0.f, 0.f};
    #pragma unroll
    for (int k = 0; k < SPLITK; k++) {
        float4 v = *(const float4*)&P[((size_t)k * BATCH + r) * 64 + c];
        s.x += v.x; s.y += v.y; s.z += v.z; s.w += v.w;
    }
    if (bias) {
        s.x += bias[c]; s.y += bias[c + 1]; s.z += bias[c + 2]; s.w += bias[c + 3];
    }
    if (mode == 0) {
        *(float4*)&outf[(size_t)r * ldc + coloff + c] = s;
    } else {
        *(uint2*)&outh[(size_t)r * ldc + coloff + c] = h4(s);
    }
}

__global__ void reduce_readnew(const float* __restrict__ PA,
                               const float* __restrict__ PB,
                               const float* __restrict__ PE,
                               const float* __restrict__ b_erase,
                               const float* __restrict__ b_add,
                               const float* __restrict__ svec,
                               __half* __restrict__ rn)
{
    int idx = blockIdx.x * blockDim.x + threadIdx.x;   // BATCH*16
    int r = idx >> 4, c = (idx & 15) * 4;
    float4 s1 = {0.f, 0.f, 0.f, 0.f}, s2 = {0.f, 0.f, 0.f, 0.f};
    float4 se = {0.f, 0.f, 0.f, 0.f}, sa = {0.f, 0.f, 0.f, 0.f};
    #pragma unroll
    for (int k = 0; k < SPLITK; k++) {
        float4 v = *(const float4*)&PA[((size_t)k * BATCH + r) * 64 + c];
        float4 u = *(const float4*)&PB[((size_t)k * BATCH + r) * 64 + c];
        float4 e = *(const float4*)&PE[((size_t)k * BATCH + r) * 128 + c];
        float4 a = *(const float4*)&PE[((size_t)k * BATCH + r) * 128 + 64 + c];
        s1.x += v.x; s1.y += v.y; s1.z += v.z; s1.w += v.w;
        s2.x += u.x; s2.y += u.y; s2.z += u.z; s2.w += u.w;
        se.x += e.x; se.y += e.y; se.z += e.z; se.w += e.w;
        sa.x += a.x; sa.y += a.y; sa.z += a.z; sa.w += a.w;
    }
    float sv = svec[r];
    float ev[4] = {se.x, se.y, se.z, se.w};
    float av[4] = {sa.x, sa.y, sa.z, sa.w};
    float v1[4] = {s1.x, s1.y, s1.z, s1.w};
    float v2[4] = {s2.x, s2.y, s2.z, s2.w};
    float4 o;
    float* op = &o.x;
    #pragma unroll
    for (int q = 0; q < 4; q++) {
        float e = sigf(ev[q] + b_erase[c + q]);
        float a = tanf_(av[q] + b_add[c + q]);
        op[q] = v1[q] - e * v2[q] + a * sv;
    }
    *(uint2*)&rn[(size_t)r * 64 + c] = h4(o);
}

// ---------------- single merged pack kernel ----------------------------------
#define N_WCAT_F4  (2048 * 160)
#define N_WRW_F4   (2048 * 128)
#define N_WEAO_F4  25600
#define N_ACAT_F4  (BATCH * 144)
#define N_RWP_F4   (BATCH * 256)
#define N_ELEM_BLK ((N_WCAT_F4 + N_WRW_F4 + N_WEAO_F4 + N_ACAT_F4 + N_RWP_F4) / 256)
#define N_MEMT_BLK 64

__global__ void pack_all(const float* __restrict__ W_ih,
                         const float* __restrict__ W_hh,
                         const float* __restrict__ W_read,
                         const float* __restrict__ W_write,
                         const float* __restrict__ W_erase,
                         const float* __restrict__ W_add,
                         const float* __restrict__ W_out,
                         const float* __restrict__ x,
                         const float* __restrict__ h_prev,
                         const float* __restrict__ rwp,
                         const float* __restrict__ mem,
                         __half* __restrict__ wcat, __half* __restrict__ wrw,
                         __half* __restrict__ wea, __half* __restrict__ wout,
                         __half* __restrict__ acat, __half* __restrict__ rwph,
                         __half* __restrict__ memT)
{
    __shared__ float s[32][33];
    if (blockIdx.x >= N_ELEM_BLK) {
        int bxm = blockIdx.x - N_ELEM_BLK;
        int k0 = (bxm & 31) * 32, v0 = (bxm >> 5) * 32;
        int tx = threadIdx.x & 31, ty = threadIdx.x >> 5;
        #pragma unroll
        for (int i = 0; i < 4; i++)
            s[ty + i * 8][tx] = mem[(size_t)(k0 + ty + i * 8) * 64 + v0 + tx];
        __syncthreads();
        #pragma unroll
        for (int i = 0; i < 4; i++)
            memT[(size_t)(v0 + ty + i * 8) * MEMN + k0 + tx] =
                __float2half_rn(s[tx][ty + i * 8]);
        return;
    }
    int idx = blockIdx.x * 256 + threadIdx.x;
    if (idx < N_WCAT_F4) {
        int n = idx / 160, q = idx % 160;
        int orig = ((n >> 3) & 3) * 512 + ((n >> 5) << 3) + (n & 7);
        float4 v = (q < 32)
            ? *(const float4*)&W_ih[(size_t)orig * 128 + q * 4]
            : *(const float4*)&W_hh[(size_t)orig * 512 + (q - 32) * 4];
        *(uint2*)&wcat[(size_t)n * KCAT + q * 4] = h4(v);
        return;
    }
    idx -= N_WCAT_F4;
    if (idx < N_WRW_F4) {
        int n = idx >> 7, q = idx & 127;
        float4 v = (n < 1024)
            ? *(const float4*)&W_read[(size_t)n * 512 + q * 4]
            : *(const float4*)&W_write[(size_t)(n - 1024) * 512 + q * 4];
        *(uint2*)&wrw[(size_t)n * 512 + q * 4] = h4(v);
        return;
    }
    idx -= N_WRW_F4;
    if (idx < N_WEAO_F4) {
        if (idx < 16384) {
            int n = idx >> 7, q = idx & 127;
            float4 v = (n < 64)
                ? *(const float4*)&W_erase[(size_t)n * 512 + q * 4]
                : *(const float4*)&W_add[(size_t)(n - 64) * 512 + q * 4];
            *(uint2*)&wea[(size_t)n * 512 + q * 4] = h4(v);
        } else {
            int j = idx - 16384;
            float4 v = *(const float4*)&W_out[(size_t)j * 4];
            *(uint2*)&wout[(size_t)j * 4] = h4(v);
        }
        return;
    }
    idx -= N_WEAO_F4;
    if (idx < N_ACAT_F4) {
        int b = idx / 144, q = idx % 144;
        float4 v; int col;
        if (q < 16) { v = *(const float4*)&x[(size_t)b * 64 + q * 4]; col = q * 4; }
        else { v = *(const float4*)&h_prev[(size_t)b * 512 + (q - 16) * 4];
               col = 128 + (q - 16) * 4; }
        *(uint2*)&acat[(size_t)b * KCAT + col] = h4(v);
        return;
    }
    idx -= N_ACAT_F4;
    {
        float4 v = *(const float4*)&rwp[(size_t)idx * 4];
        *(uint2*)&rwph[(size_t)idx * 4] = h4(v);
    }
}

// ---------------- softmax (fp16 logits in) -----------------------------------
__device__ __forceinline__ float blk_reduce(float v, bool mx, float* sh)
{
    int lane = threadIdx.x & 31, wid = threadIdx.x >> 5;
    #pragma unroll
    for (int o = 16; o > 0; o >>= 1) {
        float t = __shfl_xor_sync(0xFFFFFFFFu, v, o);
        v = mx ? fmaxf(v, t) : (v + t);
    }
    if (lane == 0) sh[wid] = v;
    __syncthreads();
    if (wid == 0) {
        float r = (lane < 8) ? sh[lane] : (mx ? -1e30f : 0.f);
        #pragma unroll
        for (int o = 4; o > 0; o >>= 1) {
            float t = __shfl_xor_sync(0xFFFFFFFFu, r, o);
            r = mx ? fmaxf(r, t) : (r + t);
        }
        if (lane == 0) sh[0] = r;
    }
    __syncthreads();
    float r = sh[0];
    __syncthreads();
    return r;
}

__global__ void softmax_fuse_kernel(const __half* __restrict__ logits,
                                    __half* __restrict__ readw,
                                    __half* __restrict__ rwprod,
                                    float* __restrict__ svec)
{
    __shared__ float sh[8];
    int b = blockIdx.x;
    int t = threadIdx.x;
    const __half* r = logits + (size_t)b * 2048;
    const __half* w = r + 1024;
    float vr[4], vw[4];
    float mr = -1e30f, mw = -1e30f;
    #pragma unroll
    for (int i = 0; i < 4; i++) {
        vr[i] = __half2float(r[t + i * 256]);
        vw[i] = __half2float(w[t + i * 256]);
        mr = fmaxf(mr, vr[i]);  mw = fmaxf(mw, vw[i]);
    }
    mr = blk_reduce(mr, true, sh);
    mw = blk_reduce(mw, true, sh);
    float er[4], ew[4], sr = 0.f, sw = 0.f;
    #pragma unroll
    for (int i = 0; i < 4; i++) {
        er[i] = __expf(vr[i] - mr); sr += er[i];
        ew[i] = __expf(vw[i] - mw); sw += ew[i];
    }
    sr = blk_reduce(sr, false, sh);
    sw = blk_reduce(sw, false, sh);
    float inv_sr = __fdividef(1.0f, sr), inv_sw = __fdividef(1.0f, sw);
    float srw = 0.f;
    #pragma unroll
    for (int i = 0; i < 4; i++) {
        float a = er[i] * inv_sr;
        float p = a * (ew[i] * inv_sw);
        readw[(size_t)b * MEMN + t + i * 256] = __float2half_rn(a);
        rwprod[(size_t)b * MEMN + t + i * 256] = __float2half_rn(p);
        srw += p;
    }
    srw = blk_reduce(srw, false, sh);
    if (t == 0) svec[b] = srw;
}

// ---------------- launch ----------------------------------------------------
extern "C" void kernel_launch(void* const* d_in, const int* in_sizes, int n_in,
                              void* d_out, int out_size)
{
    const float* x       = (const float*)d_in[0];
    const float* h_prev  = (const float*)d_in[1];
    const float* c_prev  = (const float*)d_in[2];
    const float* rwp     = (const float*)d_in[3];
    const float* memory  = (const float*)d_in[4];
    const float* W_ih    = (const float*)d_in[5];
    const float* b_ih    = (const float*)d_in[6];
    const float* W_hh    = (const float*)d_in[7];
    const float* b_hh    = (const float*)d_in[8];
    const float* W_read  = (const float*)d_in[9];
    const float* b_read  = (const float*)d_in[10];
    const float* W_write = (const float*)d_in[11];
    const float* b_write = (const float*)d_in[12];
    const float* W_erase = (const float*)d_in[13];
    const float* b_erase = (const float*)d_in[14];
    const float* W_add   = (const float*)d_in[15];
    const float* b_add   = (const float*)d_in[16];
    const float* W_out   = (const float*)d_in[17];
    const float* b_out   = (const float*)d_in[18];
    float* out = (float*)d_out;

    __half *acat, *wcat, *wrw, *wea, *wout, *memT, *rwph, *ht16, *readw, *rw, *rn, *logits;
    float *svec, *p1, *p2, *p3;
    cudaGetSymbolAddress((void**)&acat,   g_acat);
    cudaGetSymbolAddress((void**)&wcat,   g_wcat);
    cudaGetSymbolAddress((void**)&wrw,    g_wrw);
    cudaGetSymbolAddress((void**)&wea,    g_wea);
    cudaGetSymbolAddress((void**)&wout,   g_wout);
    cudaGetSymbolAddress((void**)&memT,   g_memT);
    cudaGetSymbolAddress((void**)&rwph,   g_rwph);
    cudaGetSymbolAddress((void**)&logits, g_logits);
    cudaGetSymbolAddress((void**)&ht16,   g_ht16);
    cudaGetSymbolAddress((void**)&readw,  g_readw);
    cudaGetSymbolAddress((void**)&rw,     g_rw);
    cudaGetSymbolAddress((void**)&svec,   g_s);
    cudaGetSymbolAddress((void**)&rn,     g_readnew);
    cudaGetSymbolAddress((void**)&p1,     g_p1);
    cudaGetSymbolAddress((void**)&p2,     g_p2);
    cudaGetSymbolAddress((void**)&p3,     g_p3);

    cudaFuncSetAttribute(mma_gates, cudaFuncAttributeMaxDynamicSharedMemorySize,
                         SMEM_MMA);
    cudaFuncSetAttribute(mma_logits, cudaFuncAttributeMaxDynamicSharedMemorySize,
                         SMEM_MMA);
    cudaFuncSetAttribute(mma_skinny1,
                         cudaFuncAttributeMaxDynamicSharedMemorySize, 3 * SKSTG0);
    cudaFuncSetAttribute(mma_skinny_comb,
                         cudaFuncAttributeMaxDynamicSharedMemorySize, 3 * SKSTG1);

    const int rgrid = (BATCH * 16) / 256;

    // 1) all packs + rwp fp16 + memory transpose in ONE launch
    pack_all<<<N_ELEM_BLK + N_MEMT_BLK, 256>>>(
        W_ih, W_hh, W_read, W_write, W_erase, W_add, W_out,
        x, h_prev, rwp, memory,
        wcat, wrw, wea, wout, acat, rwph, memT);

    // 2) read_prev = rwp @ memT^T -> acat[:, 64:128)
    mma_skinny1<<<dim3(BATCH / 64, SPLITK), 256, 3 * SKSTG0>>>(
        rwph, MEMN, MEMN, nullptr, 0, 0, memT, MEMN, 1, p1);
    reduce_act<<<rgrid, 256>>>(p1, nullptr, 1, nullptr, acat, KCAT, 64);

    // 3) gates GEMM + fused LSTM -> ht16   (128x128 CTA)
    mma_gates<<<dim3(16, 16), 256, SMEM_MMA>>>(
        acat, wcat, KCAT, b_ih, b_hh, c_prev, ht16);

    // 4) logits = h @ [W_read;W_write]^T  (fp16 out)
    mma_logits<<<dim3(16, 16), 256, SMEM_MMA>>>(
        ht16, wrw, CTRLN, b_read, b_write, logits);

    // 5) softmaxes + row sums
    softmax_fuse_kernel<<<BATCH, 256>>>(logits, readw, rw, svec);

    // 6) combined skinny: dual (readw,rw)@memT^T + ht@[W_erase;W_add]^T
    mma_skinny_comb<<<dim3(3 * (BATCH / 64), SPLITK), 256, 3 * SKSTG1>>>(
        readw, rw, memT, ht16, wea, p1, p2, p3);

    // 7) fused reduce -> rn (fp16)
    reduce_readnew<<<rgrid, 256>>>(p1, p2, p3, b_erase, b_add, svec, rn);

    // 8) out = [h | rn] @ W_out^T + b_out
    mma_skinny1<<<dim3(BATCH / 64, SPLITK), 256, 3 * SKSTG0>>>(
        ht16, CTRLN, CTRLN, rn, VDIM, VDIM, wout, CTRLN + VDIM, 1, p1);
    reduce_act<<<rgrid, 256>>>(p1, b_out, 0, out, nullptr, 64, 0);
}